// round 10
// baseline (speedup 1.0000x reference)
#include <cuda_runtime.h>
#include <cuda_fp16.h>
#include <math.h>
#include <stdint.h>

#define S_   2048
#define HID_ 2048
#define NH_  16
#define NKV_ 4
#define GRP_ (NH_/NKV_)   // 4
#define HD_  128
#define KVD_ (NKV_*HD_)   // 512

#define SCL_LOG2E 0.12751744f

// ---------------------------------------------------------------------------
// scratch (allocation-free: __device__ globals)
// ---------------------------------------------------------------------------
__device__ float g_q  [S_*HID_];
__device__ float g_k  [S_*KVD_];
__device__ float g_v  [S_*KVD_];

__device__ __half g_hs_hi[S_*HID_],  g_hs_lo[S_*HID_];
__device__ __half g_wq[HID_*HID_];
__device__ __half g_wk[KVD_*HID_];
__device__ __half g_wv[KVD_*HID_];
__device__ __half g_wo[HID_*HID_];
__device__ __half g_at_hi[S_*HID_],  g_at_lo[S_*HID_];

__device__ __half g_qb_hi[S_*HID_],  g_qb_lo[S_*HID_];
__device__ __half g_kb[NKV_*S_*HD_];
__device__ __half g_vb[NKV_*S_*HD_];

// ---------------------------------------------------------------------------
// PTX helpers (plain sm_103-safe)
// ---------------------------------------------------------------------------
__device__ __forceinline__ uint32_t smem_to_u32(const void* p) {
    uint32_t a;
    asm("{ .reg .u64 t; cvta.to.shared.u64 t, %1; cvt.u32.u64 %0, t; }"
        : "=r"(a) : "l"(p));
    return a;
}
__device__ __forceinline__ void cp16(uint32_t dst, const void* src) {
    asm volatile("cp.async.cg.shared.global [%0], [%1], 16;" :: "r"(dst), "l"(src));
}
#define CP_COMMIT() asm volatile("cp.async.commit_group;" ::: "memory")
#define CP_WAIT(n)  asm volatile("cp.async.wait_group %0;" :: "n"(n) : "memory")

__device__ __forceinline__ void ldm_x4(uint32_t* r, uint32_t addr) {
    asm volatile("ldmatrix.sync.aligned.m8n8.x4.shared.b16 {%0,%1,%2,%3}, [%4];"
        : "=r"(r[0]), "=r"(r[1]), "=r"(r[2]), "=r"(r[3]) : "r"(addr));
}
__device__ __forceinline__ void ldm_x2(uint32_t* r, uint32_t addr) {
    asm volatile("ldmatrix.sync.aligned.m8n8.x2.shared.b16 {%0,%1}, [%2];"
        : "=r"(r[0]), "=r"(r[1]) : "r"(addr));
}
__device__ __forceinline__ void ldm_x2t(uint32_t* r, uint32_t addr) {
    asm volatile("ldmatrix.sync.aligned.m8n8.x2.trans.shared.b16 {%0,%1}, [%2];"
        : "=r"(r[0]), "=r"(r[1]) : "r"(addr));
}
__device__ __forceinline__ void mma_f16(float* c, const uint32_t* a, const uint32_t* b) {
    asm volatile("mma.sync.aligned.m16n8k16.row.col.f32.f16.f16.f32 "
        "{%0,%1,%2,%3}, {%4,%5,%6,%7}, {%8,%9}, {%0,%1,%2,%3};"
        : "+f"(c[0]), "+f"(c[1]), "+f"(c[2]), "+f"(c[3])
        : "r"(a[0]), "r"(a[1]), "r"(a[2]), "r"(a[3]), "r"(b[0]), "r"(b[1]));
}

__device__ __forceinline__ void pack_hilo(float x, float y, uint32_t& hi, uint32_t& lo) {
    __half hx = __float2half_rn(x), hy = __float2half_rn(y);
    float rx = x - __half2float(hx), ry = y - __half2float(hy);
    __half lx = __float2half_rn(rx), ly = __float2half_rn(ry);
    union { __half2 h2; uint32_t u; } H, L;
    H.h2 = __halves2half2(hx, hy);
    L.h2 = __halves2half2(lx, ly);
    hi = H.u; lo = L.u;
}

__device__ __forceinline__ float fexp2(float x) {
    x = fmaxf(x, -126.0f);
    int e = __float2int_rn(x);
    float f = x - (float)e;
    float p = 0.0018775767f;
    p = fmaf(p, f, 0.0089893397f);
    p = fmaf(p, f, 0.0558040221f);
    p = fmaf(p, f, 0.2402264923f);
    p = fmaf(p, f, 0.6931471825f);
    p = fmaf(p, f, 1.0f);
    return __int_as_float(__float_as_int(p) + (e << 23));
}

__device__ __forceinline__ void split_f16(float v, __half* hi, __half* lo) {
    __half h = __float2half_rn(v);
    *hi = h;
    *lo = __float2half_rn(v - __half2float(h));
}

// ---------------------------------------------------------------------------
__global__ void conv_split_kernel(const float* __restrict__ src,
                                  __half* __restrict__ hi,
                                  __half* __restrict__ lo)
{
    int i = blockIdx.x * 256 + threadIdx.x;
    float4 v = ((const float4*)src)[i];
    float f[4] = {v.x, v.y, v.z, v.w};
    union { uint2 u; __half b[4]; } H, L;
    #pragma unroll
    for (int j = 0; j < 4; ++j) split_f16(f[j], &H.b[j], &L.b[j]);
    ((uint2*)hi)[i] = H.u;
    ((uint2*)lo)[i] = L.u;
}

__global__ void transpose_half2_kernel(const float* __restrict__ W0,
                                       __half* __restrict__ O0,
                                       const float* __restrict__ W1,
                                       __half* __restrict__ O1,
                                       int Kd, int Nd)
{
    __shared__ float t[32][33];
    const float* W = blockIdx.z ? W1 : W0;
    __half* out    = blockIdx.z ? O1 : O0;
    int bn = blockIdx.x * 32;
    int bk = blockIdx.y * 32;
    int x = threadIdx.x, y = threadIdx.y;
    #pragma unroll
    for (int i = 0; i < 32; i += 8)
        t[y + i][x] = W[(size_t)(bk + y + i) * Nd + bn + x];
    __syncthreads();
    #pragma unroll
    for (int i = 0; i < 32; i += 8)
        out[(size_t)(bn + y + i) * Kd + bk + x] = __float2half_rn(t[x][y + i]);
}

// ---------------------------------------------------------------------------
// Common GEMM pieces
// ---------------------------------------------------------------------------
#define TILE_B   10240              // 128 rows * 80 B
#define HTILE_B  5120               // 64 rows * 80 B

__device__ __forceinline__ void load_tile_async(uint32_t sdst,
                                                const __half* g,
                                                int ldk, int tid)
{
    int r   = tid >> 2;
    int seg = tid & 3;
    #pragma unroll
    for (int h = 0; h < 2; ++h) {
        int row = r + h * 64;
        cp16(sdst + row * 80 + seg * 16, g + (size_t)row * ldk + seg * 8);
    }
}

__device__ __forceinline__ void load_tile_async64(uint32_t sdst,
                                                  const __half* g,
                                                  int ldk, int tid)
{
    int r   = tid >> 2;       // 0..63
    int seg = tid & 3;
    cp16(sdst + r * 80 + seg * 16, g + (size_t)r * ldk + seg * 8);
}

// ---------------------------------------------------------------------------
// GEMM body A: 128x128 tile (used for Wo — 256 CTAs = single wave)
// ---------------------------------------------------------------------------
#define BUF_B    (3*TILE_B)
#define GEMM_SMEM (3*BUF_B)

__device__ __forceinline__ void load_stage(uint32_t buf,
                                           const __half* Ahi, const __half* Alo,
                                           const __half* Bh, int k0, int K, int tid)
{
    load_tile_async(buf,            Ahi + k0, K, tid);
    load_tile_async(buf +   TILE_B, Alo + k0, K, tid);
    load_tile_async(buf + 2*TILE_B, Bh  + k0, K, tid);
}

__device__ __forceinline__ void gemm_body(
    uint32_t sb,
    const __half* Ahi, const __half* Alo, const __half* Bh,
    float* C, int N, int K, int tid)
{
    const int lane = tid & 31, wid = tid >> 5;
    const int wm = wid & 1, wn = wid >> 1;

    float acc[4][4][4];
    #pragma unroll
    for (int mi = 0; mi < 4; ++mi)
        #pragma unroll
        for (int ni = 0; ni < 4; ++ni)
            #pragma unroll
            for (int q = 0; q < 4; ++q) acc[mi][ni][q] = 0.f;

    const int T = K / 32;
    load_stage(sb,         Ahi, Alo, Bh, 0,  K, tid);
    CP_COMMIT();
    load_stage(sb + BUF_B, Ahi, Alo, Bh, 32, K, tid);
    CP_COMMIT();

    const uint32_t a_lane_off = (uint32_t)((lane & 15) * 80 + (lane >> 4) * 16);
    const uint32_t b_lane_off = (uint32_t)((lane & 7) * 80 + ((lane >> 3) & 1) * 16);

    int bufidx = 0;
    for (int kt = 0; kt < T; ++kt) {
        CP_WAIT(1);
        __syncthreads();

        if (kt + 2 < T) {
            int nbi = bufidx + 2; if (nbi >= 3) nbi -= 3;
            load_stage(sb + nbi * BUF_B, Ahi, Alo, Bh, (kt + 2) * 32, K, tid);
            CP_COMMIT();
        }

        uint32_t buf = sb + bufidx * BUF_B;
        #pragma unroll
        for (int ks = 0; ks < 2; ++ks) {
            uint32_t ah[4][4], al[4][4], bh[4][2];
            uint32_t abase = buf + wm * (64 * 80) + a_lane_off + ks * 32;
            #pragma unroll
            for (int mi = 0; mi < 4; ++mi) {
                ldm_x4(ah[mi], abase + mi * (16 * 80));
                ldm_x4(al[mi], abase + TILE_B + mi * (16 * 80));
            }
            uint32_t bbase = buf + 2*TILE_B + wn * (32 * 80) + b_lane_off + ks * 32;
            #pragma unroll
            for (int ni = 0; ni < 4; ++ni)
                ldm_x2(bh[ni], bbase + ni * (8 * 80));
            #pragma unroll
            for (int mi = 0; mi < 4; ++mi)
                #pragma unroll
                for (int ni = 0; ni < 4; ++ni)
                    mma_f16(acc[mi][ni], ah[mi], bh[ni]);
            #pragma unroll
            for (int mi = 0; mi < 4; ++mi)
                #pragma unroll
                for (int ni = 0; ni < 4; ++ni)
                    mma_f16(acc[mi][ni], al[mi], bh[ni]);
        }
        if (++bufidx == 3) bufidx = 0;
    }

    #pragma unroll
    for (int mi = 0; mi < 4; ++mi) {
        int row = wm * 64 + mi * 16 + (lane >> 2);
        #pragma unroll
        for (int ni = 0; ni < 4; ++ni) {
            int col = wn * 32 + ni * 8 + (lane & 3) * 2;
            *(float2*)&C[(size_t)row * N + col] =
                make_float2(acc[mi][ni][0], acc[mi][ni][1]);
            *(float2*)&C[(size_t)(row + 8) * N + col] =
                make_float2(acc[mi][ni][2], acc[mi][ni][3]);
        }
    }
}

__global__ __launch_bounds__(256, 2)
void gemm_mma_kernel(const __half* __restrict__ Ahi,
                     const __half* __restrict__ Alo,
                     const __half* __restrict__ Bh,
                     float* __restrict__ C, int N, int K)
{
    extern __shared__ char smp[];
    uint32_t sb = smem_to_u32(smp);
    const int bm = blockIdx.y * 128, bn = blockIdx.x * 128;
    gemm_body(sb,
              Ahi + (size_t)bm * K, Alo + (size_t)bm * K,
              Bh + (size_t)bn * K,
              C + (size_t)bm * N + bn, N, K, threadIdx.x);
}

// ---------------------------------------------------------------------------
// GEMM body B: 128x64 tile (QKV — 768 CTAs, kills the 1.3-wave tail)
// 8 warps as 4m x 2n; warp tile 32x32; micro 2x4.
// ---------------------------------------------------------------------------
#define STAGE64_B (2*TILE_B + HTILE_B)   // 25600
#define GEMM64_SMEM (3*STAGE64_B)        // 76800

__device__ __forceinline__ void load_stage64(uint32_t buf,
                                             const __half* Ahi, const __half* Alo,
                                             const __half* Bh, int k0, int K, int tid)
{
    load_tile_async(buf,            Ahi + k0, K, tid);
    load_tile_async(buf +   TILE_B, Alo + k0, K, tid);
    load_tile_async64(buf + 2*TILE_B, Bh + k0, K, tid);
}

__device__ __forceinline__ void gemm_body64(
    uint32_t sb,
    const __half* Ahi, const __half* Alo, const __half* Bh,
    float* C, int N, int K, int tid)
{
    const int lane = tid & 31, wid = tid >> 5;
    const int wm = wid & 3, wn = wid >> 2;

    float acc[2][4][4];
    #pragma unroll
    for (int mi = 0; mi < 2; ++mi)
        #pragma unroll
        for (int ni = 0; ni < 4; ++ni)
            #pragma unroll
            for (int q = 0; q < 4; ++q) acc[mi][ni][q] = 0.f;

    const int T = K / 32;
    load_stage64(sb,             Ahi, Alo, Bh, 0,  K, tid);
    CP_COMMIT();
    load_stage64(sb + STAGE64_B, Ahi, Alo, Bh, 32, K, tid);
    CP_COMMIT();

    const uint32_t a_lane_off = (uint32_t)((lane & 15) * 80 + (lane >> 4) * 16);
    const uint32_t b_lane_off = (uint32_t)((lane & 7) * 80 + ((lane >> 3) & 1) * 16);

    int bufidx = 0;
    for (int kt = 0; kt < T; ++kt) {
        CP_WAIT(1);
        __syncthreads();

        if (kt + 2 < T) {
            int nbi = bufidx + 2; if (nbi >= 3) nbi -= 3;
            load_stage64(sb + nbi * STAGE64_B, Ahi, Alo, Bh, (kt + 2) * 32, K, tid);
            CP_COMMIT();
        }

        uint32_t buf = sb + bufidx * STAGE64_B;
        #pragma unroll
        for (int ks = 0; ks < 2; ++ks) {
            uint32_t ah[2][4], al[2][4], bh[4][2];
            uint32_t abase = buf + wm * (32 * 80) + a_lane_off + ks * 32;
            #pragma unroll
            for (int mi = 0; mi < 2; ++mi) {
                ldm_x4(ah[mi], abase + mi * (16 * 80));
                ldm_x4(al[mi], abase + TILE_B + mi * (16 * 80));
            }
            uint32_t bbase = buf + 2*TILE_B + wn * (32 * 80) + b_lane_off + ks * 32;
            #pragma unroll
            for (int ni = 0; ni < 4; ++ni)
                ldm_x2(bh[ni], bbase + ni * (8 * 80));
            #pragma unroll
            for (int mi = 0; mi < 2; ++mi)
                #pragma unroll
                for (int ni = 0; ni < 4; ++ni)
                    mma_f16(acc[mi][ni], ah[mi], bh[ni]);
            #pragma unroll
            for (int mi = 0; mi < 2; ++mi)
                #pragma unroll
                for (int ni = 0; ni < 4; ++ni)
                    mma_f16(acc[mi][ni], al[mi], bh[ni]);
        }
        if (++bufidx == 3) bufidx = 0;
    }

    #pragma unroll
    for (int mi = 0; mi < 2; ++mi) {
        int row = wm * 32 + mi * 16 + (lane >> 2);
        #pragma unroll
        for (int ni = 0; ni < 4; ++ni) {
            int col = wn * 32 + ni * 8 + (lane & 3) * 2;
            *(float2*)&C[(size_t)row * N + col] =
                make_float2(acc[mi][ni][0], acc[mi][ni][1]);
            *(float2*)&C[(size_t)(row + 8) * N + col] =
                make_float2(acc[mi][ni][2], acc[mi][ni][3]);
        }
    }
}

// fused QKV with 128x64 tiles: blockIdx.x 0..47 (32 Q, 8 K, 8 V)
__global__ __launch_bounds__(256, 2)
void qkv_gemm_kernel(const __half* __restrict__ Ahi,
                     const __half* __restrict__ Alo,
                     const __half* __restrict__ Wq,
                     const __half* __restrict__ Wk,
                     const __half* __restrict__ Wv,
                     float* __restrict__ Cq, float* __restrict__ Ck,
                     float* __restrict__ Cv)
{
    extern __shared__ char smp[];
    uint32_t sb = smem_to_u32(smp);
    const int nb = blockIdx.x;
    const int bm = blockIdx.y * 128;
    const __half* Bh;
    float* C;
    int N, bn;
    if (nb < 32)      { Bh = Wq; C = Cq; N = HID_; bn = nb * 64; }
    else if (nb < 40) { Bh = Wk; C = Ck; N = KVD_; bn = (nb - 32) * 64; }
    else              { Bh = Wv; C = Cv; N = KVD_; bn = (nb - 40) * 64; }
    gemm_body64(sb,
                Ahi + (size_t)bm * HID_, Alo + (size_t)bm * HID_,
                Bh + (size_t)bn * HID_,
                C + (size_t)bm * N + bn, N, HID_, threadIdx.x);
}

// ---------------------------------------------------------------------------
// RoPE
// ---------------------------------------------------------------------------
__device__ __forceinline__ void rope_pair(float x1, float x2, int pos, int d,
                                          float& o1, float& o2)
{
    float inv = exp2f((float)d * (-13.287712379549449f / 64.0f));
    float ang = (float)pos * inv;
    float sn, cs;
    sincosf(ang, &sn, &cs);
    o1 = x1 * cs - x2 * sn;
    o2 = x1 * sn + x2 * cs;
}

__global__ void rope_q_kernel(const int* __restrict__ positions,
                              __half* __restrict__ qh,
                              __half* __restrict__ ql)
{
    int idx = blockIdx.x * blockDim.x + threadIdx.x;
    int d = idx & 63;
    int s = (idx >> 6) & (S_ - 1);
    int h = idx >> 17;
    size_t base = (size_t)s * HID_ + h * HD_;
    float x1 = g_q[base + d], x2 = g_q[base + d + 64];
    float o1, o2;
    rope_pair(x1, x2, positions[s], d, o1, o2);
    o1 *= SCL_LOG2E; o2 *= SCL_LOG2E;
    split_f16(o1, &qh[base + d],      &ql[base + d]);
    split_f16(o2, &qh[base + d + 64], &ql[base + d + 64]);
}

__global__ void rope_k_kernel(const int* __restrict__ positions,
                              float* __restrict__ kout,
                              __half* __restrict__ kb)
{
    int idx = blockIdx.x * blockDim.x + threadIdx.x;
    int d  = idx & 63;
    int s  = (idx >> 6) & (S_ - 1);
    int kv = idx >> 17;
    size_t src = (size_t)s * KVD_ + kv * HD_;
    float x1 = g_k[src + d], x2 = g_k[src + d + 64];
    float o1, o2;
    rope_pair(x1, x2, positions[s], d, o1, o2);
    #pragma unroll
    for (int g = 0; g < GRP_; ++g) {
        size_t dst = ((size_t)(kv * GRP_ + g) * S_ + s) * HD_;
        kout[dst + d] = o1; kout[dst + d + 64] = o2;
    }
    size_t cb = ((size_t)kv * S_ + s) * HD_;
    kb[cb + d]      = __float2half_rn(o1);
    kb[cb + d + 64] = __float2half_rn(o2);
}

__global__ void copy_v_kernel(float* __restrict__ vout,
                              __half* __restrict__ vb)
{
    int idx = blockIdx.x * blockDim.x + threadIdx.x;
    int d4 = idx & 31;
    int s  = (idx >> 5) & (S_ - 1);
    int kv = idx >> 16;
    float4 v = *(const float4*)&g_v[(size_t)s * KVD_ + kv * HD_ + d4 * 4];
    #pragma unroll
    for (int g = 0; g < GRP_; ++g)
        *(float4*)&vout[((size_t)(kv * GRP_ + g) * S_ + s) * HD_ + d4 * 4] = v;
    size_t cb = ((size_t)kv * S_ + s) * HD_ + d4 * 4;
    float f[4] = {v.x, v.y, v.z, v.w};
    union { uint2 u; __half b[4]; } H;
    #pragma unroll
    for (int j = 0; j < 4; ++j) H.b[j] = __float2half_rn(f[j]);
    *(uint2*)&vb[cb] = H.u;
}

// ---------------------------------------------------------------------------
// Tensor-core flash attention: BQ=128, BK=64, HD=128, 8 warps.
// ---------------------------------------------------------------------------
#define FSTR  272
#define FQ_B  (128*FSTR)
#define FKV_B (64*FSTR)
#define FLASH_SMEM (2*FQ_B + 4*FKV_B)

__global__ __launch_bounds__(256, 1)
void flash_tc_kernel(const __half* __restrict__ qhp,
                     const __half* __restrict__ qlp,
                     const __half* __restrict__ khp,
                     const __half* __restrict__ vhp,
                     __half* __restrict__ ath,
                     __half* __restrict__ atl)
{
    extern __shared__ char smp[];
    const uint32_t sb = smem_to_u32(smp);
    const int tid = threadIdx.x, lane = tid & 31, w = tid >> 5;
    const int qb = 15 - blockIdx.x, h = blockIdx.y, kv = h >> 2;
    const int q0 = qb * 128;

    const uint32_t sQh = sb, sQl = sb + FQ_B;
    const uint32_t sKV = sb + 2 * FQ_B;

    {
        const __half* srch = qhp + (size_t)q0 * HID_ + h * HD_;
        const __half* srcl = qlp + (size_t)q0 * HID_ + h * HD_;
        #pragma unroll
        for (int c = tid; c < 2048; c += 256) {
            int r = c >> 4, seg = c & 15;
            cp16(sQh + r * FSTR + seg * 16, srch + (size_t)r * HID_ + seg * 8);
            cp16(sQl + r * FSTR + seg * 16, srcl + (size_t)r * HID_ + seg * 8);
        }
    }
    const __half* kb = khp + (size_t)kv * S_ * HD_;
    const __half* vb = vhp + (size_t)kv * S_ * HD_;

    auto load_kv = [&](int kt, uint32_t buf) {
        #pragma unroll
        for (int c = tid; c < 1024; c += 256) {
            int r = c >> 4, seg = c & 15;
            size_t g = (size_t)(kt * 64 + r) * HD_ + seg * 8;
            uint32_t so = r * FSTR + seg * 16;
            cp16(buf + so,         kb + g);
            cp16(buf + FKV_B + so, vb + g);
        }
    };
    load_kv(0, sKV);
    CP_COMMIT();

    float o[16][4];
    #pragma unroll
    for (int j = 0; j < 16; ++j)
        #pragma unroll
        for (int q = 0; q < 4; ++q) o[j][q] = 0.f;
    float m0 = -1e30f, m1 = -1e30f, l0 = 0.f, l1 = 0.f;

    const int last = 2 * qb + 1;
    const uint32_t a_off  = (lane & 15) * FSTR + (lane >> 4) * 16;
    const uint32_t bk_off = (lane & 7) * FSTR + ((lane >> 3) & 1) * 16;
    const uint32_t bv_off = (lane & 15) * FSTR;
    const int r0 = q0 + w * 16 + (lane >> 2);

    for (int kt = 0; kt <= last; ++kt) {
        if (kt < last) {
            load_kv(kt + 1, sKV + ((kt + 1) & 1) * 2 * FKV_B);
            CP_COMMIT();
            CP_WAIT(1);
        } else {
            CP_WAIT(0);
        }
        __syncthreads();

        const uint32_t bK = sKV + (kt & 1) * 2 * FKV_B;
        const uint32_t bV = bK + FKV_B;

        float s[8][4];
        #pragma unroll
        for (int j = 0; j < 8; ++j)
            #pragma unroll
            for (int q = 0; q < 4; ++q) s[j][q] = 0.f;

        #pragma unroll
        for (int ks = 0; ks < 8; ++ks) {
            uint32_t ah[4], al[4], bh2[8][2];
            ldm_x4(ah, sQh + w * (16 * FSTR) + a_off + ks * 32);
            ldm_x4(al, sQl + w * (16 * FSTR) + a_off + ks * 32);
            #pragma unroll
            for (int j = 0; j < 8; ++j)
                ldm_x2(bh2[j], bK + j * (8 * FSTR) + bk_off + ks * 32);
            #pragma unroll
            for (int j = 0; j < 8; ++j)
                mma_f16(s[j], ah, bh2[j]);
            #pragma unroll
            for (int j = 0; j < 8; ++j)
                mma_f16(s[j], al, bh2[j]);
        }

        if (kt >= 2 * qb) {
            #pragma unroll
            for (int j = 0; j < 8; ++j) {
                int col = kt * 64 + j * 8 + (lane & 3) * 2;
                if (col     > r0)     s[j][0] = -3e4f;
                if (col + 1 > r0)     s[j][1] = -3e4f;
                if (col     > r0 + 8) s[j][2] = -3e4f;
                if (col + 1 > r0 + 8) s[j][3] = -3e4f;
            }
        }

        float mx0 = -3e4f, mx1 = -3e4f;
        #pragma unroll
        for (int j = 0; j < 8; ++j) {
            mx0 = fmaxf(mx0, fmaxf(s[j][0], s[j][1]));
            mx1 = fmaxf(mx1, fmaxf(s[j][2], s[j][3]));
        }
        mx0 = fmaxf(mx0, __shfl_xor_sync(0xffffffffu, mx0, 1));
        mx0 = fmaxf(mx0, __shfl_xor_sync(0xffffffffu, mx0, 2));
        mx1 = fmaxf(mx1, __shfl_xor_sync(0xffffffffu, mx1, 1));
        mx1 = fmaxf(mx1, __shfl_xor_sync(0xffffffffu, mx1, 2));

        const float mn0 = fmaxf(m0, mx0), mn1 = fmaxf(m1, mx1);
        const float al0 = fexp2(m0 - mn0), al1 = fexp2(m1 - mn1);
        m0 = mn0; m1 = mn1;

        float sum0 = 0.f, sum1 = 0.f;
        #pragma unroll
        for (int j = 0; j < 8; ++j) {
            s[j][0] = fexp2(s[j][0] - mn0);
            s[j][1] = fexp2(s[j][1] - mn0);
            s[j][2] = fexp2(s[j][2] - mn1);
            s[j][3] = fexp2(s[j][3] - mn1);
            sum0 += s[j][0] + s[j][1];
            sum1 += s[j][2] + s[j][3];
        }
        sum0 += __shfl_xor_sync(0xffffffffu, sum0, 1);
        sum0 += __shfl_xor_sync(0xffffffffu, sum0, 2);
        sum1 += __shfl_xor_sync(0xffffffffu, sum1, 1);
        sum1 += __shfl_xor_sync(0xffffffffu, sum1, 2);
        l0 = l0 * al0 + sum0;
        l1 = l1 * al1 + sum1;

        #pragma unroll
        for (int j = 0; j < 16; ++j) {
            o[j][0] *= al0; o[j][1] *= al0;
            o[j][2] *= al1; o[j][3] *= al1;
        }

        #pragma unroll
        for (int pk = 0; pk < 4; ++pk) {
            uint32_t phi[4], plo[4], vv[16][2];
            pack_hilo(s[2*pk][0],   s[2*pk][1],   phi[0], plo[0]);
            pack_hilo(s[2*pk][2],   s[2*pk][3],   phi[1], plo[1]);
            pack_hilo(s[2*pk+1][0], s[2*pk+1][1], phi[2], plo[2]);
            pack_hilo(s[2*pk+1][2], s[2*pk+1][3], phi[3], plo[3]);
            #pragma unroll
            for (int j = 0; j < 16; ++j) {
                ldm_x2t(vv[j], bV + pk * (16 * FSTR) + bv_off + j * 16);
                mma_f16(o[j], phi, vv[j]);
            }
            #pragma unroll
            for (int j = 0; j < 16; ++j)
                mma_f16(o[j], plo, vv[j]);
        }
        __syncthreads();
    }

    const float inv0 = 1.f / l0, inv1 = 1.f / l1;
    #pragma unroll
    for (int j = 0; j < 16; ++j) {
        int col = j * 8 + (lane & 3) * 2;
        uint32_t hi, lo;
        pack_hilo(o[j][0] * inv0, o[j][1] * inv0, hi, lo);
        size_t off0 = (size_t)r0 * HID_ + h * HD_ + col;
        *(uint32_t*)&ath[off0] = hi;
        *(uint32_t*)&atl[off0] = lo;
        pack_hilo(o[j][2] * inv1, o[j][3] * inv1, hi, lo);
        size_t off1 = (size_t)(r0 + 8) * HID_ + h * HD_ + col;
        *(uint32_t*)&ath[off1] = hi;
        *(uint32_t*)&atl[off1] = lo;
    }
}

// ---------------------------------------------------------------------------
extern "C" void kernel_launch(void* const* d_in, const int* in_sizes, int n_in,
                              void* d_out, int out_size)
{
    const float* hs  = (const float*)d_in[0];
    const int*   pos = (const int*)  d_in[1];
    const float* Wq  = (const float*)d_in[3];
    const float* Wk  = (const float*)d_in[4];
    const float* Wv  = (const float*)d_in[5];
    const float* Wo  = (const float*)d_in[6];

    float* out  = (float*)d_out;
    float* kout = out  + (size_t)S_ * HID_;
    float* vout = kout + (size_t)NH_ * S_ * HD_;

    float *qp, *kp, *vp;
    cudaGetSymbolAddress((void**)&qp, g_q);
    cudaGetSymbolAddress((void**)&kp, g_k);
    cudaGetSymbolAddress((void**)&vp, g_v);
    __half *hsh, *hsl, *wq, *wk, *wv, *wo, *ath, *atl;
    __half *qbh, *qbl, *kb, *vb;
    cudaGetSymbolAddress((void**)&hsh, g_hs_hi); cudaGetSymbolAddress((void**)&hsl, g_hs_lo);
    cudaGetSymbolAddress((void**)&wq, g_wq);
    cudaGetSymbolAddress((void**)&wk, g_wk);
    cudaGetSymbolAddress((void**)&wv, g_wv);
    cudaGetSymbolAddress((void**)&wo, g_wo);
    cudaGetSymbolAddress((void**)&ath, g_at_hi); cudaGetSymbolAddress((void**)&atl, g_at_lo);
    cudaGetSymbolAddress((void**)&qbh, g_qb_hi); cudaGetSymbolAddress((void**)&qbl, g_qb_lo);
    cudaGetSymbolAddress((void**)&kb, g_kb);
    cudaGetSymbolAddress((void**)&vb, g_vb);

    cudaFuncSetAttribute(qkv_gemm_kernel,
                         cudaFuncAttributeMaxDynamicSharedMemorySize, GEMM64_SMEM);
    cudaFuncSetAttribute(gemm_mma_kernel,
                         cudaFuncAttributeMaxDynamicSharedMemorySize, GEMM_SMEM);
    cudaFuncSetAttribute(flash_tc_kernel,
                         cudaFuncAttributeMaxDynamicSharedMemorySize, FLASH_SMEM);

    conv_split_kernel<<<(S_*HID_/4)/256, 256>>>(hs, hsh, hsl);
    transpose_half2_kernel<<<dim3(HID_/32, HID_/32, 2), dim3(32,8)>>>(
        Wq, wq, Wo, wo, HID_, HID_);
    transpose_half2_kernel<<<dim3(KVD_/32, HID_/32, 2), dim3(32,8)>>>(
        Wk, wk, Wv, wv, HID_, KVD_);

    // fused QKV: 128x64 tiles, 768 CTAs (tail-balanced)
    qkv_gemm_kernel<<<dim3(48, S_/128), 256, GEMM64_SMEM>>>(
        hsh, hsl, wq, wk, wv, qp, kp, vp);

    rope_q_kernel<<<(NH_*S_*64)/256, 256>>>(pos, qbh, qbl);
    rope_k_kernel<<<(NKV_*S_*64)/256, 256>>>(pos, kout, kb);
    copy_v_kernel<<<(NKV_*S_*32)/256, 256>>>(vout, vb);

    flash_tc_kernel<<<dim3(16, NH_), 256, FLASH_SMEM>>>(
        qbh, qbl, kb, vb, ath, atl);

    gemm_mma_kernel<<<dim3(HID_/128, S_/128), 256, GEMM_SMEM>>>(
        ath, atl, wo, out, HID_, HID_);
}

// round 11
// speedup vs baseline: 1.0709x; 1.0709x over previous
#include <cuda_runtime.h>
#include <cuda_fp16.h>
#include <math.h>
#include <stdint.h>

#define S_   2048
#define HID_ 2048
#define NH_  16
#define NKV_ 4
#define GRP_ (NH_/NKV_)   // 4
#define HD_  128
#define KVD_ (NKV_*HD_)   // 512

#define SCL_LOG2E 0.12751744f

// ---------------------------------------------------------------------------
// scratch (allocation-free: __device__ globals)
// ---------------------------------------------------------------------------
__device__ __half g_hs_hi[S_*HID_],  g_hs_lo[S_*HID_];
__device__ __half g_wq[HID_*HID_];
__device__ __half g_wk[KVD_*HID_];
__device__ __half g_wv[KVD_*HID_];
__device__ __half g_wo[HID_*HID_];
__device__ __half g_at_hi[S_*HID_],  g_at_lo[S_*HID_];

__device__ __half g_qb_hi[S_*HID_],  g_qb_lo[S_*HID_];
__device__ __half g_kb[NKV_*S_*HD_];
__device__ __half g_vb[NKV_*S_*HD_];

// ---------------------------------------------------------------------------
// PTX helpers (plain sm_103-safe)
// ---------------------------------------------------------------------------
__device__ __forceinline__ uint32_t smem_to_u32(const void* p) {
    uint32_t a;
    asm("{ .reg .u64 t; cvta.to.shared.u64 t, %1; cvt.u32.u64 %0, t; }"
        : "=r"(a) : "l"(p));
    return a;
}
__device__ __forceinline__ void cp16(uint32_t dst, const void* src) {
    asm volatile("cp.async.cg.shared.global [%0], [%1], 16;" :: "r"(dst), "l"(src));
}
#define CP_COMMIT() asm volatile("cp.async.commit_group;" ::: "memory")
#define CP_WAIT(n)  asm volatile("cp.async.wait_group %0;" :: "n"(n) : "memory")

__device__ __forceinline__ void ldm_x4(uint32_t* r, uint32_t addr) {
    asm volatile("ldmatrix.sync.aligned.m8n8.x4.shared.b16 {%0,%1,%2,%3}, [%4];"
        : "=r"(r[0]), "=r"(r[1]), "=r"(r[2]), "=r"(r[3]) : "r"(addr));
}
__device__ __forceinline__ void ldm_x2(uint32_t* r, uint32_t addr) {
    asm volatile("ldmatrix.sync.aligned.m8n8.x2.shared.b16 {%0,%1}, [%2];"
        : "=r"(r[0]), "=r"(r[1]) : "r"(addr));
}
__device__ __forceinline__ void ldm_x2t(uint32_t* r, uint32_t addr) {
    asm volatile("ldmatrix.sync.aligned.m8n8.x2.trans.shared.b16 {%0,%1}, [%2];"
        : "=r"(r[0]), "=r"(r[1]) : "r"(addr));
}
__device__ __forceinline__ void mma_f16(float* c, const uint32_t* a, const uint32_t* b) {
    asm volatile("mma.sync.aligned.m16n8k16.row.col.f32.f16.f16.f32 "
        "{%0,%1,%2,%3}, {%4,%5,%6,%7}, {%8,%9}, {%0,%1,%2,%3};"
        : "+f"(c[0]), "+f"(c[1]), "+f"(c[2]), "+f"(c[3])
        : "r"(a[0]), "r"(a[1]), "r"(a[2]), "r"(a[3]), "r"(b[0]), "r"(b[1]));
}

__device__ __forceinline__ void pack_hilo(float x, float y, uint32_t& hi, uint32_t& lo) {
    __half hx = __float2half_rn(x), hy = __float2half_rn(y);
    float rx = x - __half2float(hx), ry = y - __half2float(hy);
    __half lx = __float2half_rn(rx), ly = __float2half_rn(ry);
    union { __half2 h2; uint32_t u; } H, L;
    H.h2 = __halves2half2(hx, hy);
    L.h2 = __halves2half2(lx, ly);
    hi = H.u; lo = L.u;
}

__device__ __forceinline__ float fexp2(float x) {
    x = fmaxf(x, -126.0f);
    int e = __float2int_rn(x);
    float f = x - (float)e;
    float p = 0.0018775767f;
    p = fmaf(p, f, 0.0089893397f);
    p = fmaf(p, f, 0.0558040221f);
    p = fmaf(p, f, 0.2402264923f);
    p = fmaf(p, f, 0.6931471825f);
    p = fmaf(p, f, 1.0f);
    return __int_as_float(__float_as_int(p) + (e << 23));
}

__device__ __forceinline__ void split_f16(float v, __half* hi, __half* lo) {
    __half h = __float2half_rn(v);
    *hi = h;
    *lo = __float2half_rn(v - __half2float(h));
}

__device__ __forceinline__ void rope_pair(float x1, float x2, int pos, int d,
                                          float& o1, float& o2)
{
    float inv = exp2f((float)d * (-13.287712379549449f / 64.0f));
    float ang = (float)pos * inv;
    float sn, cs;
    sincosf(ang, &sn, &cs);
    o1 = x1 * cs - x2 * sn;
    o2 = x1 * sn + x2 * cs;
}

// ---------------------------------------------------------------------------
__global__ void conv_split_kernel(const float* __restrict__ src,
                                  __half* __restrict__ hi,
                                  __half* __restrict__ lo)
{
    int i = blockIdx.x * 256 + threadIdx.x;
    float4 v = ((const float4*)src)[i];
    float f[4] = {v.x, v.y, v.z, v.w};
    union { uint2 u; __half b[4]; } H, L;
    #pragma unroll
    for (int j = 0; j < 4; ++j) split_f16(f[j], &H.b[j], &L.b[j]);
    ((uint2*)hi)[i] = H.u;
    ((uint2*)lo)[i] = L.u;
}

__global__ void transpose_half2_kernel(const float* __restrict__ W0,
                                       __half* __restrict__ O0,
                                       const float* __restrict__ W1,
                                       __half* __restrict__ O1,
                                       int Kd, int Nd)
{
    __shared__ float t[32][33];
    const float* W = blockIdx.z ? W1 : W0;
    __half* out    = blockIdx.z ? O1 : O0;
    int bn = blockIdx.x * 32;
    int bk = blockIdx.y * 32;
    int x = threadIdx.x, y = threadIdx.y;
    #pragma unroll
    for (int i = 0; i < 32; i += 8)
        t[y + i][x] = W[(size_t)(bk + y + i) * Nd + bn + x];
    __syncthreads();
    #pragma unroll
    for (int i = 0; i < 32; i += 8)
        out[(size_t)(bn + y + i) * Kd + bk + x] = __float2half_rn(t[x][y + i]);
}

// ---------------------------------------------------------------------------
// GEMM pieces: 128x128 tile, K-chunks of 32, 3-stage cp.async pipeline
// ---------------------------------------------------------------------------
#define TILE_B   10240
#define BUF_B    (3*TILE_B)
#define GEMM_SMEM (3*BUF_B)    // 92160

__device__ __forceinline__ void load_tile_async(uint32_t sdst,
                                                const __half* g,
                                                int ldk, int tid)
{
    int r   = tid >> 2;
    int seg = tid & 3;
    #pragma unroll
    for (int h = 0; h < 2; ++h) {
        int row = r + h * 64;
        cp16(sdst + row * 80 + seg * 16, g + (size_t)row * ldk + seg * 8);
    }
}

__device__ __forceinline__ void load_stage(uint32_t buf,
                                           const __half* Ahi, const __half* Alo,
                                           const __half* Bh, int k0, int K, int tid)
{
    load_tile_async(buf,            Ahi + k0, K, tid);
    load_tile_async(buf +   TILE_B, Alo + k0, K, tid);
    load_tile_async(buf + 2*TILE_B, Bh  + k0, K, tid);
}

// mainloop producing acc[4][4][4] (warp tile 64x32, 8 warps 2m x 4n)
__device__ __forceinline__ void gemm_mainloop(
    uint32_t sb,
    const __half* Ahi, const __half* Alo, const __half* Bh,
    int K, int tid, float acc[4][4][4])
{
    const int lane = tid & 31, wid = tid >> 5;
    const int wm = wid & 1, wn = wid >> 1;

    #pragma unroll
    for (int mi = 0; mi < 4; ++mi)
        #pragma unroll
        for (int ni = 0; ni < 4; ++ni)
            #pragma unroll
            for (int q = 0; q < 4; ++q) acc[mi][ni][q] = 0.f;

    const int T = K / 32;
    load_stage(sb,         Ahi, Alo, Bh, 0,  K, tid);
    CP_COMMIT();
    load_stage(sb + BUF_B, Ahi, Alo, Bh, 32, K, tid);
    CP_COMMIT();

    const uint32_t a_lane_off = (uint32_t)((lane & 15) * 80 + (lane >> 4) * 16);
    const uint32_t b_lane_off = (uint32_t)((lane & 7) * 80 + ((lane >> 3) & 1) * 16);

    int bufidx = 0;
    for (int kt = 0; kt < T; ++kt) {
        if (kt < T - 1) { CP_WAIT(1); } else { CP_WAIT(0); }
        __syncthreads();

        if (kt + 2 < T) {
            int nbi = bufidx + 2; if (nbi >= 3) nbi -= 3;
            load_stage(sb + nbi * BUF_B, Ahi, Alo, Bh, (kt + 2) * 32, K, tid);
            CP_COMMIT();
        }

        uint32_t buf = sb + bufidx * BUF_B;
        #pragma unroll
        for (int ks = 0; ks < 2; ++ks) {
            uint32_t ah[4][4], al[4][4], bh[4][2];
            uint32_t abase = buf + wm * (64 * 80) + a_lane_off + ks * 32;
            #pragma unroll
            for (int mi = 0; mi < 4; ++mi) {
                ldm_x4(ah[mi], abase + mi * (16 * 80));
                ldm_x4(al[mi], abase + TILE_B + mi * (16 * 80));
            }
            uint32_t bbase = buf + 2*TILE_B + wn * (32 * 80) + b_lane_off + ks * 32;
            #pragma unroll
            for (int ni = 0; ni < 4; ++ni)
                ldm_x2(bh[ni], bbase + ni * (8 * 80));
            #pragma unroll
            for (int mi = 0; mi < 4; ++mi)
                #pragma unroll
                for (int ni = 0; ni < 4; ++ni)
                    mma_f16(acc[mi][ni], ah[mi], bh[ni]);
            #pragma unroll
            for (int mi = 0; mi < 4; ++mi)
                #pragma unroll
                for (int ni = 0; ni < 4; ++ni)
                    mma_f16(acc[mi][ni], al[mi], bh[ni]);
        }
        if (++bufidx == 3) bufidx = 0;
    }
}

// ---------------------------------------------------------------------------
// Wo GEMM: plain fp32 output
// ---------------------------------------------------------------------------
__global__ __launch_bounds__(256, 2)
void gemm_mma_kernel(const __half* __restrict__ Ahi,
                     const __half* __restrict__ Alo,
                     const __half* __restrict__ Bh,
                     float* __restrict__ C, int N, int K)
{
    extern __shared__ char smp[];
    uint32_t sb = smem_to_u32(smp);
    const int tid = threadIdx.x;
    const int lane = tid & 31, wid = tid >> 5;
    const int wm = wid & 1, wn = wid >> 1;
    const int bm = blockIdx.y * 128, bn = blockIdx.x * 128;

    float acc[4][4][4];
    gemm_mainloop(sb,
                  Ahi + (size_t)bm * K, Alo + (size_t)bm * K,
                  Bh + (size_t)bn * K, K, tid, acc);

    float* Cb = C + (size_t)bm * N + bn;
    #pragma unroll
    for (int mi = 0; mi < 4; ++mi) {
        int row = wm * 64 + mi * 16 + (lane >> 2);
        #pragma unroll
        for (int ni = 0; ni < 4; ++ni) {
            int col = wn * 32 + ni * 8 + (lane & 3) * 2;
            *(float2*)&Cb[(size_t)row * N + col] =
                make_float2(acc[mi][ni][0], acc[mi][ni][1]);
            *(float2*)&Cb[(size_t)(row + 8) * N + col] =
                make_float2(acc[mi][ni][2], acc[mi][ni][3]);
        }
    }
}

// ---------------------------------------------------------------------------
// Fused QKV GEMM + RoPE/split/repeat epilogue.
// blockIdx.x: 0..15 Q-head tiles, 16..19 K heads, 20..23 V heads.
// Epilogue stages the fp32 tile in smem (reuses pipeline buffers), then:
//   Q: rope + *scale -> qbh/qbl
//   K: rope -> kout (fp32, repeated 4x) + kb (fp16 compact)
//   V: copy -> vout (fp32, repeated 4x) + vb (fp16 compact)
// ---------------------------------------------------------------------------
#define TSTR 130   // fp32 smem tile row stride (padding)

__global__ __launch_bounds__(256, 2)
void qkv_gemm_kernel(const __half* __restrict__ Ahi,
                     const __half* __restrict__ Alo,
                     const __half* __restrict__ Wq,
                     const __half* __restrict__ Wk,
                     const __half* __restrict__ Wv,
                     const int* __restrict__ pos,
                     __half* __restrict__ qbh, __half* __restrict__ qbl,
                     float* __restrict__ kout, __half* __restrict__ kb,
                     float* __restrict__ vout, __half* __restrict__ vb)
{
    extern __shared__ char smp[];
    uint32_t sb = smem_to_u32(smp);
    const int tid = threadIdx.x;
    const int lane = tid & 31, wid = tid >> 5;
    const int wm = wid & 1, wn = wid >> 1;
    const int nb = blockIdx.x;
    const int bm = blockIdx.y * 128;

    const __half* Bh;
    int bn;
    if (nb < 16)      { Bh = Wq; bn = nb * 128; }
    else if (nb < 20) { Bh = Wk; bn = (nb - 16) * 128; }
    else              { Bh = Wv; bn = (nb - 20) * 128; }

    float acc[4][4][4];
    gemm_mainloop(sb,
                  Ahi + (size_t)bm * HID_, Alo + (size_t)bm * HID_,
                  Bh + (size_t)bn * HID_, HID_, tid, acc);

    // stage fp32 tile in smem (overwrite pipeline buffers)
    __syncthreads();
    float* t = (float*)smp;
    #pragma unroll
    for (int mi = 0; mi < 4; ++mi) {
        int row = wm * 64 + mi * 16 + (lane >> 2);
        #pragma unroll
        for (int ni = 0; ni < 4; ++ni) {
            int col = wn * 32 + ni * 8 + (lane & 3) * 2;
            *(float2*)&t[row * TSTR + col]       = make_float2(acc[mi][ni][0], acc[mi][ni][1]);
            *(float2*)&t[(row + 8) * TSTR + col] = make_float2(acc[mi][ni][2], acc[mi][ni][3]);
        }
    }
    __syncthreads();

    if (nb < 16) {
        const int h = nb;
        for (int i = tid; i < 128 * 64; i += 256) {
            int sl = i >> 6, d = i & 63;
            int sg = bm + sl;
            float x1 = t[sl * TSTR + d], x2 = t[sl * TSTR + d + 64];
            float o1, o2;
            rope_pair(x1, x2, pos[sg], d, o1, o2);
            o1 *= SCL_LOG2E; o2 *= SCL_LOG2E;
            size_t base = (size_t)sg * HID_ + h * HD_;
            split_f16(o1, &qbh[base + d],      &qbl[base + d]);
            split_f16(o2, &qbh[base + d + 64], &qbl[base + d + 64]);
        }
    } else if (nb < 20) {
        const int kv = nb - 16;
        for (int i = tid; i < 128 * 64; i += 256) {
            int sl = i >> 6, d = i & 63;
            int sg = bm + sl;
            float x1 = t[sl * TSTR + d], x2 = t[sl * TSTR + d + 64];
            float o1, o2;
            rope_pair(x1, x2, pos[sg], d, o1, o2);
            #pragma unroll
            for (int g = 0; g < GRP_; ++g) {
                size_t dst = ((size_t)(kv * GRP_ + g) * S_ + sg) * HD_;
                kout[dst + d] = o1; kout[dst + d + 64] = o2;
            }
            size_t cb = ((size_t)kv * S_ + sg) * HD_;
            kb[cb + d]      = __float2half_rn(o1);
            kb[cb + d + 64] = __float2half_rn(o2);
        }
    } else {
        const int kv = nb - 20;
        for (int i = tid; i < 128 * 64; i += 256) {
            int sl = i >> 6, d2 = (i & 63) * 2;
            int sg = bm + sl;
            float v0 = t[sl * TSTR + d2], v1 = t[sl * TSTR + d2 + 1];
            #pragma unroll
            for (int g = 0; g < GRP_; ++g) {
                size_t dst = ((size_t)(kv * GRP_ + g) * S_ + sg) * HD_ + d2;
                *(float2*)&vout[dst] = make_float2(v0, v1);
            }
            size_t cb = ((size_t)kv * S_ + sg) * HD_ + d2;
            union { __half2 h2; uint32_t u; } H;
            H.h2 = __halves2half2(__float2half_rn(v0), __float2half_rn(v1));
            *(uint32_t*)&vb[cb] = H.u;
        }
    }
}

// ---------------------------------------------------------------------------
// Tensor-core flash attention: BQ=128, BK=64, HD=128, 8 warps.
// ---------------------------------------------------------------------------
#define FSTR  272
#define FQ_B  (128*FSTR)
#define FKV_B (64*FSTR)
#define FLASH_SMEM (2*FQ_B + 4*FKV_B)

__global__ __launch_bounds__(256, 1)
void flash_tc_kernel(const __half* __restrict__ qhp,
                     const __half* __restrict__ qlp,
                     const __half* __restrict__ khp,
                     const __half* __restrict__ vhp,
                     __half* __restrict__ ath,
                     __half* __restrict__ atl)
{
    extern __shared__ char smp[];
    const uint32_t sb = smem_to_u32(smp);
    const int tid = threadIdx.x, lane = tid & 31, w = tid >> 5;
    const int qb = 15 - blockIdx.x, h = blockIdx.y, kv = h >> 2;
    const int q0 = qb * 128;

    const uint32_t sQh = sb, sQl = sb + FQ_B;
    const uint32_t sKV = sb + 2 * FQ_B;

    {
        const __half* srch = qhp + (size_t)q0 * HID_ + h * HD_;
        const __half* srcl = qlp + (size_t)q0 * HID_ + h * HD_;
        #pragma unroll
        for (int c = tid; c < 2048; c += 256) {
            int r = c >> 4, seg = c & 15;
            cp16(sQh + r * FSTR + seg * 16, srch + (size_t)r * HID_ + seg * 8);
            cp16(sQl + r * FSTR + seg * 16, srcl + (size_t)r * HID_ + seg * 8);
        }
    }
    const __half* kb = khp + (size_t)kv * S_ * HD_;
    const __half* vb = vhp + (size_t)kv * S_ * HD_;

    auto load_kv = [&](int kt, uint32_t buf) {
        #pragma unroll
        for (int c = tid; c < 1024; c += 256) {
            int r = c >> 4, seg = c & 15;
            size_t g = (size_t)(kt * 64 + r) * HD_ + seg * 8;
            uint32_t so = r * FSTR + seg * 16;
            cp16(buf + so,         kb + g);
            cp16(buf + FKV_B + so, vb + g);
        }
    };
    load_kv(0, sKV);
    CP_COMMIT();

    float o[16][4];
    #pragma unroll
    for (int j = 0; j < 16; ++j)
        #pragma unroll
        for (int q = 0; q < 4; ++q) o[j][q] = 0.f;
    float m0 = -1e30f, m1 = -1e30f, l0 = 0.f, l1 = 0.f;

    const int last = 2 * qb + 1;
    const uint32_t a_off  = (lane & 15) * FSTR + (lane >> 4) * 16;
    const uint32_t bk_off = (lane & 7) * FSTR + ((lane >> 3) & 1) * 16;
    const uint32_t bv_off = (lane & 15) * FSTR;
    const int r0 = q0 + w * 16 + (lane >> 2);

    for (int kt = 0; kt <= last; ++kt) {
        if (kt < last) {
            load_kv(kt + 1, sKV + ((kt + 1) & 1) * 2 * FKV_B);
            CP_COMMIT();
            CP_WAIT(1);
        } else {
            CP_WAIT(0);
        }
        __syncthreads();

        const uint32_t bK = sKV + (kt & 1) * 2 * FKV_B;
        const uint32_t bV = bK + FKV_B;

        float s[8][4];
        #pragma unroll
        for (int j = 0; j < 8; ++j)
            #pragma unroll
            for (int q = 0; q < 4; ++q) s[j][q] = 0.f;

        #pragma unroll
        for (int ks = 0; ks < 8; ++ks) {
            uint32_t ah[4], al[4], bh2[8][2];
            ldm_x4(ah, sQh + w * (16 * FSTR) + a_off + ks * 32);
            ldm_x4(al, sQl + w * (16 * FSTR) + a_off + ks * 32);
            #pragma unroll
            for (int j = 0; j < 8; ++j)
                ldm_x2(bh2[j], bK + j * (8 * FSTR) + bk_off + ks * 32);
            #pragma unroll
            for (int j = 0; j < 8; ++j)
                mma_f16(s[j], ah, bh2[j]);
            #pragma unroll
            for (int j = 0; j < 8; ++j)
                mma_f16(s[j], al, bh2[j]);
        }

        if (kt >= 2 * qb) {
            #pragma unroll
            for (int j = 0; j < 8; ++j) {
                int col = kt * 64 + j * 8 + (lane & 3) * 2;
                if (col     > r0)     s[j][0] = -3e4f;
                if (col + 1 > r0)     s[j][1] = -3e4f;
                if (col     > r0 + 8) s[j][2] = -3e4f;
                if (col + 1 > r0 + 8) s[j][3] = -3e4f;
            }
        }

        float mx0 = -3e4f, mx1 = -3e4f;
        #pragma unroll
        for (int j = 0; j < 8; ++j) {
            mx0 = fmaxf(mx0, fmaxf(s[j][0], s[j][1]));
            mx1 = fmaxf(mx1, fmaxf(s[j][2], s[j][3]));
        }
        mx0 = fmaxf(mx0, __shfl_xor_sync(0xffffffffu, mx0, 1));
        mx0 = fmaxf(mx0, __shfl_xor_sync(0xffffffffu, mx0, 2));
        mx1 = fmaxf(mx1, __shfl_xor_sync(0xffffffffu, mx1, 1));
        mx1 = fmaxf(mx1, __shfl_xor_sync(0xffffffffu, mx1, 2));

        const float mn0 = fmaxf(m0, mx0), mn1 = fmaxf(m1, mx1);
        const float al0 = fexp2(m0 - mn0), al1 = fexp2(m1 - mn1);
        m0 = mn0; m1 = mn1;

        float sum0 = 0.f, sum1 = 0.f;
        #pragma unroll
        for (int j = 0; j < 8; ++j) {
            s[j][0] = fexp2(s[j][0] - mn0);
            s[j][1] = fexp2(s[j][1] - mn0);
            s[j][2] = fexp2(s[j][2] - mn1);
            s[j][3] = fexp2(s[j][3] - mn1);
            sum0 += s[j][0] + s[j][1];
            sum1 += s[j][2] + s[j][3];
        }
        sum0 += __shfl_xor_sync(0xffffffffu, sum0, 1);
        sum0 += __shfl_xor_sync(0xffffffffu, sum0, 2);
        sum1 += __shfl_xor_sync(0xffffffffu, sum1, 1);
        sum1 += __shfl_xor_sync(0xffffffffu, sum1, 2);
        l0 = l0 * al0 + sum0;
        l1 = l1 * al1 + sum1;

        #pragma unroll
        for (int j = 0; j < 16; ++j) {
            o[j][0] *= al0; o[j][1] *= al0;
            o[j][2] *= al1; o[j][3] *= al1;
        }

        #pragma unroll
        for (int pk = 0; pk < 4; ++pk) {
            uint32_t phi[4], plo[4], vv[16][2];
            pack_hilo(s[2*pk][0],   s[2*pk][1],   phi[0], plo[0]);
            pack_hilo(s[2*pk][2],   s[2*pk][3],   phi[1], plo[1]);
            pack_hilo(s[2*pk+1][0], s[2*pk+1][1], phi[2], plo[2]);
            pack_hilo(s[2*pk+1][2], s[2*pk+1][3], phi[3], plo[3]);
            #pragma unroll
            for (int j = 0; j < 16; ++j) {
                ldm_x2t(vv[j], bV + pk * (16 * FSTR) + bv_off + j * 16);
                mma_f16(o[j], phi, vv[j]);
            }
            #pragma unroll
            for (int j = 0; j < 16; ++j)
                mma_f16(o[j], plo, vv[j]);
        }
        __syncthreads();
    }

    const float inv0 = 1.f / l0, inv1 = 1.f / l1;
    #pragma unroll
    for (int j = 0; j < 16; ++j) {
        int col = j * 8 + (lane & 3) * 2;
        uint32_t hi, lo;
        pack_hilo(o[j][0] * inv0, o[j][1] * inv0, hi, lo);
        size_t off0 = (size_t)r0 * HID_ + h * HD_ + col;
        *(uint32_t*)&ath[off0] = hi;
        *(uint32_t*)&atl[off0] = lo;
        pack_hilo(o[j][2] * inv1, o[j][3] * inv1, hi, lo);
        size_t off1 = (size_t)(r0 + 8) * HID_ + h * HD_ + col;
        *(uint32_t*)&ath[off1] = hi;
        *(uint32_t*)&atl[off1] = lo;
    }
}

// ---------------------------------------------------------------------------
extern "C" void kernel_launch(void* const* d_in, const int* in_sizes, int n_in,
                              void* d_out, int out_size)
{
    const float* hs  = (const float*)d_in[0];
    const int*   pos = (const int*)  d_in[1];
    const float* Wq  = (const float*)d_in[3];
    const float* Wk  = (const float*)d_in[4];
    const float* Wv  = (const float*)d_in[5];
    const float* Wo  = (const float*)d_in[6];

    float* out  = (float*)d_out;
    float* kout = out  + (size_t)S_ * HID_;
    float* vout = kout + (size_t)NH_ * S_ * HD_;

    __half *hsh, *hsl, *wq, *wk, *wv, *wo, *ath, *atl;
    __half *qbh, *qbl, *kb, *vb;
    cudaGetSymbolAddress((void**)&hsh, g_hs_hi); cudaGetSymbolAddress((void**)&hsl, g_hs_lo);
    cudaGetSymbolAddress((void**)&wq, g_wq);
    cudaGetSymbolAddress((void**)&wk, g_wk);
    cudaGetSymbolAddress((void**)&wv, g_wv);
    cudaGetSymbolAddress((void**)&wo, g_wo);
    cudaGetSymbolAddress((void**)&ath, g_at_hi); cudaGetSymbolAddress((void**)&atl, g_at_lo);
    cudaGetSymbolAddress((void**)&qbh, g_qb_hi); cudaGetSymbolAddress((void**)&qbl, g_qb_lo);
    cudaGetSymbolAddress((void**)&kb, g_kb);
    cudaGetSymbolAddress((void**)&vb, g_vb);

    cudaFuncSetAttribute(qkv_gemm_kernel,
                         cudaFuncAttributeMaxDynamicSharedMemorySize, GEMM_SMEM);
    cudaFuncSetAttribute(gemm_mma_kernel,
                         cudaFuncAttributeMaxDynamicSharedMemorySize, GEMM_SMEM);
    cudaFuncSetAttribute(flash_tc_kernel,
                         cudaFuncAttributeMaxDynamicSharedMemorySize, FLASH_SMEM);

    conv_split_kernel<<<(S_*HID_/4)/256, 256>>>(hs, hsh, hsl);
    transpose_half2_kernel<<<dim3(HID_/32, HID_/32, 2), dim3(32,8)>>>(
        Wq, wq, Wo, wo, HID_, HID_);
    transpose_half2_kernel<<<dim3(KVD_/32, HID_/32, 2), dim3(32,8)>>>(
        Wk, wk, Wv, wv, HID_, KVD_);

    // fused QKV GEMM + rope/split/repeat epilogue (128x128 tiles)
    qkv_gemm_kernel<<<dim3(24, S_/128), 256, GEMM_SMEM>>>(
        hsh, hsl, wq, wk, wv, pos, qbh, qbl, kout, kb, vout, vb);

    flash_tc_kernel<<<dim3(16, NH_), 256, FLASH_SMEM>>>(
        qbh, qbl, kb, vb, ath, atl);

    gemm_mma_kernel<<<dim3(HID_/128, S_/128), 256, GEMM_SMEM>>>(
        ath, atl, wo, out, HID_, HID_);
}

// round 12
// speedup vs baseline: 1.1455x; 1.0696x over previous
#include <cuda_runtime.h>
#include <cuda_fp16.h>
#include <math.h>
#include <stdint.h>

#define S_   2048
#define HID_ 2048
#define NH_  16
#define NKV_ 4
#define GRP_ (NH_/NKV_)   // 4
#define HD_  128
#define KVD_ (NKV_*HD_)   // 512

#define SCL_LOG2E 0.12751744f

// ---------------------------------------------------------------------------
// scratch (allocation-free: __device__ globals)
// ---------------------------------------------------------------------------
__device__ float g_q  [S_*HID_];
__device__ float g_k  [S_*KVD_];
__device__ float g_v  [S_*KVD_];

__device__ __half g_hs_hi[S_*HID_],  g_hs_lo[S_*HID_];
__device__ __half g_wq[HID_*HID_];
__device__ __half g_wk[KVD_*HID_];
__device__ __half g_wv[KVD_*HID_];
__device__ __half g_wo[HID_*HID_];
__device__ __half g_at_hi[S_*HID_],  g_at_lo[S_*HID_];

__device__ __half g_qb_hi[S_*HID_],  g_qb_lo[S_*HID_];
__device__ __half g_kb[NKV_*S_*HD_];
__device__ __half g_vb[NKV_*S_*HD_];

// ---------------------------------------------------------------------------
// PTX helpers (plain sm_103-safe)
// ---------------------------------------------------------------------------
__device__ __forceinline__ uint32_t smem_to_u32(const void* p) {
    uint32_t a;
    asm("{ .reg .u64 t; cvta.to.shared.u64 t, %1; cvt.u32.u64 %0, t; }"
        : "=r"(a) : "l"(p));
    return a;
}
__device__ __forceinline__ void cp16(uint32_t dst, const void* src) {
    asm volatile("cp.async.cg.shared.global [%0], [%1], 16;" :: "r"(dst), "l"(src));
}
#define CP_COMMIT() asm volatile("cp.async.commit_group;" ::: "memory")
#define CP_WAIT(n)  asm volatile("cp.async.wait_group %0;" :: "n"(n) : "memory")

__device__ __forceinline__ void ldm_x4(uint32_t* r, uint32_t addr) {
    asm volatile("ldmatrix.sync.aligned.m8n8.x4.shared.b16 {%0,%1,%2,%3}, [%4];"
        : "=r"(r[0]), "=r"(r[1]), "=r"(r[2]), "=r"(r[3]) : "r"(addr));
}
__device__ __forceinline__ void ldm_x2(uint32_t* r, uint32_t addr) {
    asm volatile("ldmatrix.sync.aligned.m8n8.x2.shared.b16 {%0,%1}, [%2];"
        : "=r"(r[0]), "=r"(r[1]) : "r"(addr));
}
__device__ __forceinline__ void ldm_x2t(uint32_t* r, uint32_t addr) {
    asm volatile("ldmatrix.sync.aligned.m8n8.x2.trans.shared.b16 {%0,%1}, [%2];"
        : "=r"(r[0]), "=r"(r[1]) : "r"(addr));
}
__device__ __forceinline__ void mma_f16(float* c, const uint32_t* a, const uint32_t* b) {
    asm volatile("mma.sync.aligned.m16n8k16.row.col.f32.f16.f16.f32 "
        "{%0,%1,%2,%3}, {%4,%5,%6,%7}, {%8,%9}, {%0,%1,%2,%3};"
        : "+f"(c[0]), "+f"(c[1]), "+f"(c[2]), "+f"(c[3])
        : "r"(a[0]), "r"(a[1]), "r"(a[2]), "r"(a[3]), "r"(b[0]), "r"(b[1]));
}

__device__ __forceinline__ void pack_hilo(float x, float y, uint32_t& hi, uint32_t& lo) {
    __half hx = __float2half_rn(x), hy = __float2half_rn(y);
    float rx = x - __half2float(hx), ry = y - __half2float(hy);
    __half lx = __float2half_rn(rx), ly = __float2half_rn(ry);
    union { __half2 h2; uint32_t u; } H, L;
    H.h2 = __halves2half2(hx, hy);
    L.h2 = __halves2half2(lx, ly);
    hi = H.u; lo = L.u;
}

__device__ __forceinline__ float fexp2(float x) {
    x = fmaxf(x, -126.0f);
    int e = __float2int_rn(x);
    float f = x - (float)e;
    float p = 0.0018775767f;
    p = fmaf(p, f, 0.0089893397f);
    p = fmaf(p, f, 0.0558040221f);
    p = fmaf(p, f, 0.2402264923f);
    p = fmaf(p, f, 0.6931471825f);
    p = fmaf(p, f, 1.0f);
    return __int_as_float(__float_as_int(p) + (e << 23));
}

__device__ __forceinline__ void split_f16(float v, __half* hi, __half* lo) {
    __half h = __float2half_rn(v);
    *hi = h;
    *lo = __float2half_rn(v - __half2float(h));
}

__device__ __forceinline__ void rope_pair(float x1, float x2, int pos, int d,
                                          float& o1, float& o2)
{
    float inv = exp2f((float)d * (-13.287712379549449f / 64.0f));
    float ang = (float)pos * inv;
    float sn, cs;
    sincosf(ang, &sn, &cs);
    o1 = x1 * cs - x2 * sn;
    o2 = x1 * sn + x2 * cs;
}

// ---------------------------------------------------------------------------
__global__ void conv_split_kernel(const float* __restrict__ src,
                                  __half* __restrict__ hi,
                                  __half* __restrict__ lo)
{
    int i = blockIdx.x * 256 + threadIdx.x;
    float4 v = ((const float4*)src)[i];
    float f[4] = {v.x, v.y, v.z, v.w};
    union { uint2 u; __half b[4]; } H, L;
    #pragma unroll
    for (int j = 0; j < 4; ++j) split_f16(f[j], &H.b[j], &L.b[j]);
    ((uint2*)hi)[i] = H.u;
    ((uint2*)lo)[i] = L.u;
}

__global__ void transpose_half2_kernel(const float* __restrict__ W0,
                                       __half* __restrict__ O0,
                                       const float* __restrict__ W1,
                                       __half* __restrict__ O1,
                                       int Kd, int Nd)
{
    __shared__ float t[32][33];
    const float* W = blockIdx.z ? W1 : W0;
    __half* out    = blockIdx.z ? O1 : O0;
    int bn = blockIdx.x * 32;
    int bk = blockIdx.y * 32;
    int x = threadIdx.x, y = threadIdx.y;
    #pragma unroll
    for (int i = 0; i < 32; i += 8)
        t[y + i][x] = W[(size_t)(bk + y + i) * Nd + bn + x];
    __syncthreads();
    #pragma unroll
    for (int i = 0; i < 32; i += 8)
        out[(size_t)(bn + y + i) * Kd + bk + x] = __float2half_rn(t[x][y + i]);
}

// ---------------------------------------------------------------------------
// GEMM: 128x128 tile, K-chunks of 32, 3-stage cp.async pipeline, 2 CTAs/SM
// ---------------------------------------------------------------------------
#define TILE_B   10240
#define BUF_B    (3*TILE_B)
#define GEMM_SMEM (3*BUF_B)

__device__ __forceinline__ void load_tile_async(uint32_t sdst,
                                                const __half* g,
                                                int ldk, int tid)
{
    int r   = tid >> 2;
    int seg = tid & 3;
    #pragma unroll
    for (int h = 0; h < 2; ++h) {
        int row = r + h * 64;
        cp16(sdst + row * 80 + seg * 16, g + (size_t)row * ldk + seg * 8);
    }
}

__device__ __forceinline__ void load_stage(uint32_t buf,
                                           const __half* Ahi, const __half* Alo,
                                           const __half* Bh, int k0, int K, int tid)
{
    load_tile_async(buf,            Ahi + k0, K, tid);
    load_tile_async(buf +   TILE_B, Alo + k0, K, tid);
    load_tile_async(buf + 2*TILE_B, Bh  + k0, K, tid);
}

__device__ __forceinline__ void gemm_body(
    uint32_t sb,
    const __half* Ahi, const __half* Alo, const __half* Bh,
    float* C, int N, int K, int tid)
{
    const int lane = tid & 31, wid = tid >> 5;
    const int wm = wid & 1, wn = wid >> 1;

    float acc[4][4][4];
    #pragma unroll
    for (int mi = 0; mi < 4; ++mi)
        #pragma unroll
        for (int ni = 0; ni < 4; ++ni)
            #pragma unroll
            for (int q = 0; q < 4; ++q) acc[mi][ni][q] = 0.f;

    const int T = K / 32;
    load_stage(sb,         Ahi, Alo, Bh, 0,  K, tid);
    CP_COMMIT();
    load_stage(sb + BUF_B, Ahi, Alo, Bh, 32, K, tid);
    CP_COMMIT();

    const uint32_t a_lane_off = (uint32_t)((lane & 15) * 80 + (lane >> 4) * 16);
    const uint32_t b_lane_off = (uint32_t)((lane & 7) * 80 + ((lane >> 3) & 1) * 16);

    int bufidx = 0;
    for (int kt = 0; kt < T; ++kt) {
        if (kt < T - 1) { CP_WAIT(1); } else { CP_WAIT(0); }
        __syncthreads();

        if (kt + 2 < T) {
            int nbi = bufidx + 2; if (nbi >= 3) nbi -= 3;
            load_stage(sb + nbi * BUF_B, Ahi, Alo, Bh, (kt + 2) * 32, K, tid);
            CP_COMMIT();
        }

        uint32_t buf = sb + bufidx * BUF_B;
        #pragma unroll
        for (int ks = 0; ks < 2; ++ks) {
            uint32_t ah[4][4], al[4][4], bh[4][2];
            uint32_t abase = buf + wm * (64 * 80) + a_lane_off + ks * 32;
            #pragma unroll
            for (int mi = 0; mi < 4; ++mi) {
                ldm_x4(ah[mi], abase + mi * (16 * 80));
                ldm_x4(al[mi], abase + TILE_B + mi * (16 * 80));
            }
            uint32_t bbase = buf + 2*TILE_B + wn * (32 * 80) + b_lane_off + ks * 32;
            #pragma unroll
            for (int ni = 0; ni < 4; ++ni)
                ldm_x2(bh[ni], bbase + ni * (8 * 80));
            #pragma unroll
            for (int mi = 0; mi < 4; ++mi)
                #pragma unroll
                for (int ni = 0; ni < 4; ++ni)
                    mma_f16(acc[mi][ni], ah[mi], bh[ni]);
            #pragma unroll
            for (int mi = 0; mi < 4; ++mi)
                #pragma unroll
                for (int ni = 0; ni < 4; ++ni)
                    mma_f16(acc[mi][ni], al[mi], bh[ni]);
        }
        if (++bufidx == 3) bufidx = 0;
    }

    #pragma unroll
    for (int mi = 0; mi < 4; ++mi) {
        int row = wm * 64 + mi * 16 + (lane >> 2);
        #pragma unroll
        for (int ni = 0; ni < 4; ++ni) {
            int col = wn * 32 + ni * 8 + (lane & 3) * 2;
            *(float2*)&C[(size_t)row * N + col] =
                make_float2(acc[mi][ni][0], acc[mi][ni][1]);
            *(float2*)&C[(size_t)(row + 8) * N + col] =
                make_float2(acc[mi][ni][2], acc[mi][ni][3]);
        }
    }
}

__global__ __launch_bounds__(256, 2)
void qkv_gemm_kernel(const __half* __restrict__ Ahi,
                     const __half* __restrict__ Alo,
                     const __half* __restrict__ Wq,
                     const __half* __restrict__ Wk,
                     const __half* __restrict__ Wv,
                     float* __restrict__ Cq, float* __restrict__ Ck,
                     float* __restrict__ Cv)
{
    extern __shared__ char smp[];
    uint32_t sb = smem_to_u32(smp);
    const int nb = blockIdx.x;
    const int bm = blockIdx.y * 128;
    const __half* Bh;
    float* C;
    int N, bn;
    if (nb < 16)      { Bh = Wq; C = Cq; N = HID_; bn = nb * 128; }
    else if (nb < 20) { Bh = Wk; C = Ck; N = KVD_; bn = (nb - 16) * 128; }
    else              { Bh = Wv; C = Cv; N = KVD_; bn = (nb - 20) * 128; }
    gemm_body(sb,
              Ahi + (size_t)bm * HID_, Alo + (size_t)bm * HID_,
              Bh + (size_t)bn * HID_,
              C + (size_t)bm * N + bn, N, HID_, threadIdx.x);
}

__global__ __launch_bounds__(256, 2)
void gemm_mma_kernel(const __half* __restrict__ Ahi,
                     const __half* __restrict__ Alo,
                     const __half* __restrict__ Bh,
                     float* __restrict__ C, int N, int K)
{
    extern __shared__ char smp[];
    uint32_t sb = smem_to_u32(smp);
    const int bm = blockIdx.y * 128, bn = blockIdx.x * 128;
    gemm_body(sb,
              Ahi + (size_t)bm * K, Alo + (size_t)bm * K,
              Bh + (size_t)bn * K,
              C + (size_t)bm * N + bn, N, K, threadIdx.x);
}

// ---------------------------------------------------------------------------
// RoPE / layout kernels
// ---------------------------------------------------------------------------
__global__ void rope_q_kernel(const int* __restrict__ positions,
                              __half* __restrict__ qh,
                              __half* __restrict__ ql)
{
    int idx = blockIdx.x * blockDim.x + threadIdx.x;
    int d = idx & 63;
    int s = (idx >> 6) & (S_ - 1);
    int h = idx >> 17;
    size_t base = (size_t)s * HID_ + h * HD_;
    float x1 = g_q[base + d], x2 = g_q[base + d + 64];
    float o1, o2;
    rope_pair(x1, x2, positions[s], d, o1, o2);
    o1 *= SCL_LOG2E; o2 *= SCL_LOG2E;
    split_f16(o1, &qh[base + d],      &ql[base + d]);
    split_f16(o2, &qh[base + d + 64], &ql[base + d + 64]);
}

__global__ void rope_k_kernel(const int* __restrict__ positions,
                              float* __restrict__ kout,
                              __half* __restrict__ kb)
{
    int idx = blockIdx.x * blockDim.x + threadIdx.x;
    int d  = idx & 63;
    int s  = (idx >> 6) & (S_ - 1);
    int kv = idx >> 17;
    size_t src = (size_t)s * KVD_ + kv * HD_;
    float x1 = g_k[src + d], x2 = g_k[src + d + 64];
    float o1, o2;
    rope_pair(x1, x2, positions[s], d, o1, o2);
    #pragma unroll
    for (int g = 0; g < GRP_; ++g) {
        size_t dst = ((size_t)(kv * GRP_ + g) * S_ + s) * HD_;
        kout[dst + d] = o1; kout[dst + d + 64] = o2;
    }
    size_t cb = ((size_t)kv * S_ + s) * HD_;
    kb[cb + d]      = __float2half_rn(o1);
    kb[cb + d + 64] = __float2half_rn(o2);
}

__global__ void copy_v_kernel(float* __restrict__ vout,
                              __half* __restrict__ vb)
{
    int idx = blockIdx.x * blockDim.x + threadIdx.x;
    int d4 = idx & 31;
    int s  = (idx >> 5) & (S_ - 1);
    int kv = idx >> 16;
    float4 v = *(const float4*)&g_v[(size_t)s * KVD_ + kv * HD_ + d4 * 4];
    #pragma unroll
    for (int g = 0; g < GRP_; ++g)
        *(float4*)&vout[((size_t)(kv * GRP_ + g) * S_ + s) * HD_ + d4 * 4] = v;
    size_t cb = ((size_t)kv * S_ + s) * HD_ + d4 * 4;
    float f[4] = {v.x, v.y, v.z, v.w};
    union { uint2 u; __half b[4]; } H;
    #pragma unroll
    for (int j = 0; j < 4; ++j) H.b[j] = __float2half_rn(f[j]);
    *(uint2*)&vb[cb] = H.u;
}

// ---------------------------------------------------------------------------
// Tensor-core flash attention: BQ=64, BK=64, HD=128, 4 warps, 2 CTAs/SM.
// ---------------------------------------------------------------------------
#define FSTR  272
#define FQ_B  (64*FSTR)                 // 17408
#define FKV_B (64*FSTR)                 // 17408
#define FLASH_SMEM (2*FQ_B + 4*FKV_B)   // 104448

__global__ __launch_bounds__(128, 2)
void flash_tc_kernel(const __half* __restrict__ qhp,
                     const __half* __restrict__ qlp,
                     const __half* __restrict__ khp,
                     const __half* __restrict__ vhp,
                     __half* __restrict__ ath,
                     __half* __restrict__ atl)
{
    extern __shared__ char smp[];
    const uint32_t sb = smem_to_u32(smp);
    const int tid = threadIdx.x, lane = tid & 31, w = tid >> 5;   // w: 0..3
    const int qb = 31 - blockIdx.x, h = blockIdx.y, kv = h >> 2;
    const int q0 = qb * 64;

    const uint32_t sQh = sb, sQl = sb + FQ_B;
    const uint32_t sKV = sb + 2 * FQ_B;   // per stage: [Kh | Vh]

    {
        const __half* srch = qhp + (size_t)q0 * HID_ + h * HD_;
        const __half* srcl = qlp + (size_t)q0 * HID_ + h * HD_;
        #pragma unroll
        for (int c = tid; c < 1024; c += 128) {
            int r = c >> 4, seg = c & 15;
            cp16(sQh + r * FSTR + seg * 16, srch + (size_t)r * HID_ + seg * 8);
            cp16(sQl + r * FSTR + seg * 16, srcl + (size_t)r * HID_ + seg * 8);
        }
    }
    const __half* kb = khp + (size_t)kv * S_ * HD_;
    const __half* vb = vhp + (size_t)kv * S_ * HD_;

    auto load_kv = [&](int kt, uint32_t buf) {
        #pragma unroll
        for (int c = tid; c < 1024; c += 128) {
            int r = c >> 4, seg = c & 15;
            size_t g = (size_t)(kt * 64 + r) * HD_ + seg * 8;
            uint32_t so = r * FSTR + seg * 16;
            cp16(buf + so,         kb + g);
            cp16(buf + FKV_B + so, vb + g);
        }
    };
    load_kv(0, sKV);
    CP_COMMIT();

    float o[16][4];
    #pragma unroll
    for (int j = 0; j < 16; ++j)
        #pragma unroll
        for (int q = 0; q < 4; ++q) o[j][q] = 0.f;
    float m0 = -1e30f, m1 = -1e30f, l0 = 0.f, l1 = 0.f;

    const int last = qb;
    const uint32_t a_off  = (lane & 15) * FSTR + (lane >> 4) * 16;
    const uint32_t bk_off = (lane & 7) * FSTR + ((lane >> 3) & 1) * 16;
    const uint32_t bv_off = (lane & 15) * FSTR;
    const int r0 = q0 + w * 16 + (lane >> 2);

    for (int kt = 0; kt <= last; ++kt) {
        if (kt < last) {
            load_kv(kt + 1, sKV + ((kt + 1) & 1) * 2 * FKV_B);
            CP_COMMIT();
            CP_WAIT(1);
        } else {
            CP_WAIT(0);
        }
        __syncthreads();

        const uint32_t bK = sKV + (kt & 1) * 2 * FKV_B;
        const uint32_t bV = bK + FKV_B;

        // ---- scores S = (Qh+Ql) Kh^T ----
        float s[8][4];
        #pragma unroll
        for (int j = 0; j < 8; ++j)
            #pragma unroll
            for (int q = 0; q < 4; ++q) s[j][q] = 0.f;

        #pragma unroll
        for (int ks = 0; ks < 8; ++ks) {
            uint32_t ah[4], al[4], bh2[8][2];
            ldm_x4(ah, sQh + w * (16 * FSTR) + a_off + ks * 32);
            ldm_x4(al, sQl + w * (16 * FSTR) + a_off + ks * 32);
            #pragma unroll
            for (int j = 0; j < 8; ++j)
                ldm_x2(bh2[j], bK + j * (8 * FSTR) + bk_off + ks * 32);
            #pragma unroll
            for (int j = 0; j < 8; ++j)
                mma_f16(s[j], ah, bh2[j]);
            #pragma unroll
            for (int j = 0; j < 8; ++j)
                mma_f16(s[j], al, bh2[j]);
        }

        // ---- causal mask (diagonal block only) ----
        if (kt == qb) {
            #pragma unroll
            for (int j = 0; j < 8; ++j) {
                int col = kt * 64 + j * 8 + (lane & 3) * 2;
                if (col     > r0)     s[j][0] = -3e4f;
                if (col + 1 > r0)     s[j][1] = -3e4f;
                if (col     > r0 + 8) s[j][2] = -3e4f;
                if (col + 1 > r0 + 8) s[j][3] = -3e4f;
            }
        }

        // ---- row max ----
        float mx0 = -3e4f, mx1 = -3e4f;
        #pragma unroll
        for (int j = 0; j < 8; ++j) {
            mx0 = fmaxf(mx0, fmaxf(s[j][0], s[j][1]));
            mx1 = fmaxf(mx1, fmaxf(s[j][2], s[j][3]));
        }
        mx0 = fmaxf(mx0, __shfl_xor_sync(0xffffffffu, mx0, 1));
        mx0 = fmaxf(mx0, __shfl_xor_sync(0xffffffffu, mx0, 2));
        mx1 = fmaxf(mx1, __shfl_xor_sync(0xffffffffu, mx1, 1));
        mx1 = fmaxf(mx1, __shfl_xor_sync(0xffffffffu, mx1, 2));

        const float mn0 = fmaxf(m0, mx0), mn1 = fmaxf(m1, mx1);
        const float al0 = fexp2(m0 - mn0), al1 = fexp2(m1 - mn1);
        m0 = mn0; m1 = mn1;

        // ---- exp + row sum ----
        float sum0 = 0.f, sum1 = 0.f;
        #pragma unroll
        for (int j = 0; j < 8; ++j) {
            s[j][0] = fexp2(s[j][0] - mn0);
            s[j][1] = fexp2(s[j][1] - mn0);
            s[j][2] = fexp2(s[j][2] - mn1);
            s[j][3] = fexp2(s[j][3] - mn1);
            sum0 += s[j][0] + s[j][1];
            sum1 += s[j][2] + s[j][3];
        }
        sum0 += __shfl_xor_sync(0xffffffffu, sum0, 1);
        sum0 += __shfl_xor_sync(0xffffffffu, sum0, 2);
        sum1 += __shfl_xor_sync(0xffffffffu, sum1, 1);
        sum1 += __shfl_xor_sync(0xffffffffu, sum1, 2);
        l0 = l0 * al0 + sum0;
        l1 = l1 * al1 + sum1;

        // ---- rescale O ----
        #pragma unroll
        for (int j = 0; j < 16; ++j) {
            o[j][0] *= al0; o[j][1] *= al0;
            o[j][2] *= al1; o[j][3] *= al1;
        }

        // ---- O += (Ph+Pl) Vh ----
        #pragma unroll
        for (int pk = 0; pk < 4; ++pk) {
            uint32_t phi[4], plo[4], vv[16][2];
            pack_hilo(s[2*pk][0],   s[2*pk][1],   phi[0], plo[0]);
            pack_hilo(s[2*pk][2],   s[2*pk][3],   phi[1], plo[1]);
            pack_hilo(s[2*pk+1][0], s[2*pk+1][1], phi[2], plo[2]);
            pack_hilo(s[2*pk+1][2], s[2*pk+1][3], phi[3], plo[3]);
            #pragma unroll
            for (int j = 0; j < 16; ++j) {
                ldm_x2t(vv[j], bV + pk * (16 * FSTR) + bv_off + j * 16);
                mma_f16(o[j], phi, vv[j]);
            }
            #pragma unroll
            for (int j = 0; j < 16; ++j)
                mma_f16(o[j], plo, vv[j]);
        }
        __syncthreads();
    }

    // ---- epilogue ----
    const float inv0 = 1.f / l0, inv1 = 1.f / l1;
    #pragma unroll
    for (int j = 0; j < 16; ++j) {
        int col = j * 8 + (lane & 3) * 2;
        uint32_t hi, lo;
        pack_hilo(o[j][0] * inv0, o[j][1] * inv0, hi, lo);
        size_t off0 = (size_t)r0 * HID_ + h * HD_ + col;
        *(uint32_t*)&ath[off0] = hi;
        *(uint32_t*)&atl[off0] = lo;
        pack_hilo(o[j][2] * inv1, o[j][3] * inv1, hi, lo);
        size_t off1 = (size_t)(r0 + 8) * HID_ + h * HD_ + col;
        *(uint32_t*)&ath[off1] = hi;
        *(uint32_t*)&atl[off1] = lo;
    }
}

// ---------------------------------------------------------------------------
extern "C" void kernel_launch(void* const* d_in, const int* in_sizes, int n_in,
                              void* d_out, int out_size)
{
    const float* hs  = (const float*)d_in[0];
    const int*   pos = (const int*)  d_in[1];
    const float* Wq  = (const float*)d_in[3];
    const float* Wk  = (const float*)d_in[4];
    const float* Wv  = (const float*)d_in[5];
    const float* Wo  = (const float*)d_in[6];

    float* out  = (float*)d_out;
    float* kout = out  + (size_t)S_ * HID_;
    float* vout = kout + (size_t)NH_ * S_ * HD_;

    float *qp, *kp, *vp;
    cudaGetSymbolAddress((void**)&qp, g_q);
    cudaGetSymbolAddress((void**)&kp, g_k);
    cudaGetSymbolAddress((void**)&vp, g_v);
    __half *hsh, *hsl, *wq, *wk, *wv, *wo, *ath, *atl;
    __half *qbh, *qbl, *kb, *vb;
    cudaGetSymbolAddress((void**)&hsh, g_hs_hi); cudaGetSymbolAddress((void**)&hsl, g_hs_lo);
    cudaGetSymbolAddress((void**)&wq, g_wq);
    cudaGetSymbolAddress((void**)&wk, g_wk);
    cudaGetSymbolAddress((void**)&wv, g_wv);
    cudaGetSymbolAddress((void**)&wo, g_wo);
    cudaGetSymbolAddress((void**)&ath, g_at_hi); cudaGetSymbolAddress((void**)&atl, g_at_lo);
    cudaGetSymbolAddress((void**)&qbh, g_qb_hi); cudaGetSymbolAddress((void**)&qbl, g_qb_lo);
    cudaGetSymbolAddress((void**)&kb, g_kb);
    cudaGetSymbolAddress((void**)&vb, g_vb);

    cudaFuncSetAttribute(qkv_gemm_kernel,
                         cudaFuncAttributeMaxDynamicSharedMemorySize, GEMM_SMEM);
    cudaFuncSetAttribute(gemm_mma_kernel,
                         cudaFuncAttributeMaxDynamicSharedMemorySize, GEMM_SMEM);
    cudaFuncSetAttribute(flash_tc_kernel,
                         cudaFuncAttributeMaxDynamicSharedMemorySize, FLASH_SMEM);

    conv_split_kernel<<<(S_*HID_/4)/256, 256>>>(hs, hsh, hsl);
    transpose_half2_kernel<<<dim3(HID_/32, HID_/32, 2), dim3(32,8)>>>(
        Wq, wq, Wo, wo, HID_, HID_);
    transpose_half2_kernel<<<dim3(KVD_/32, HID_/32, 2), dim3(32,8)>>>(
        Wk, wk, Wv, wv, HID_, KVD_);

    qkv_gemm_kernel<<<dim3(24, S_/128), 256, GEMM_SMEM>>>(
        hsh, hsl, wq, wk, wv, qp, kp, vp);

    rope_q_kernel<<<(NH_*S_*64)/256, 256>>>(pos, qbh, qbl);
    rope_k_kernel<<<(NKV_*S_*64)/256, 256>>>(pos, kout, kb);
    copy_v_kernel<<<(NKV_*S_*32)/256, 256>>>(vout, vb);

    // flash: BQ=64, 128-thread CTAs, 2 CTAs/SM, longest-first
    flash_tc_kernel<<<dim3(32, NH_), 128, FLASH_SMEM>>>(
        qbh, qbl, kb, vb, ath, atl);

    gemm_mma_kernel<<<dim3(HID_/128, S_/128), 256, GEMM_SMEM>>>(
        ath, atl, wo, out, HID_, HID_);
}

// round 13
// speedup vs baseline: 1.3339x; 1.1645x over previous
#include <cuda_runtime.h>
#include <cuda_fp16.h>
#include <math.h>
#include <stdint.h>

#define S_   2048
#define HID_ 2048
#define NH_  16
#define NKV_ 4
#define GRP_ (NH_/NKV_)   // 4
#define HD_  128
#define KVD_ (NKV_*HD_)   // 512

#define SCL_LOG2E 0.12751744f

// ---------------------------------------------------------------------------
// scratch (allocation-free: __device__ globals)
// ---------------------------------------------------------------------------
__device__ float g_q  [S_*HID_];
__device__ float g_k  [S_*KVD_];
__device__ float g_v  [S_*KVD_];

__device__ __half g_hs_hi[S_*HID_],  g_hs_lo[S_*HID_];
__device__ __half g_wq[HID_*HID_];
__device__ __half g_wk[KVD_*HID_];
__device__ __half g_wv[KVD_*HID_];
__device__ __half g_wo[HID_*HID_];
__device__ __half g_at[S_*HID_];          // attn out, single fp16

__device__ __half g_qb_hi[S_*HID_],  g_qb_lo[S_*HID_];
__device__ __half g_kb[NKV_*S_*HD_];
__device__ __half g_vb[NKV_*S_*HD_];

// ---------------------------------------------------------------------------
// PTX helpers (plain sm_103-safe)
// ---------------------------------------------------------------------------
__device__ __forceinline__ uint32_t smem_to_u32(const void* p) {
    uint32_t a;
    asm("{ .reg .u64 t; cvta.to.shared.u64 t, %1; cvt.u32.u64 %0, t; }"
        : "=r"(a) : "l"(p));
    return a;
}
__device__ __forceinline__ void cp16(uint32_t dst, const void* src) {
    asm volatile("cp.async.cg.shared.global [%0], [%1], 16;" :: "r"(dst), "l"(src));
}
#define CP_COMMIT() asm volatile("cp.async.commit_group;" ::: "memory")
#define CP_WAIT(n)  asm volatile("cp.async.wait_group %0;" :: "n"(n) : "memory")

__device__ __forceinline__ void ldm_x4(uint32_t* r, uint32_t addr) {
    asm volatile("ldmatrix.sync.aligned.m8n8.x4.shared.b16 {%0,%1,%2,%3}, [%4];"
        : "=r"(r[0]), "=r"(r[1]), "=r"(r[2]), "=r"(r[3]) : "r"(addr));
}
__device__ __forceinline__ void ldm_x2(uint32_t* r, uint32_t addr) {
    asm volatile("ldmatrix.sync.aligned.m8n8.x2.shared.b16 {%0,%1}, [%2];"
        : "=r"(r[0]), "=r"(r[1]) : "r"(addr));
}
__device__ __forceinline__ void ldm_x2t(uint32_t* r, uint32_t addr) {
    asm volatile("ldmatrix.sync.aligned.m8n8.x2.trans.shared.b16 {%0,%1}, [%2];"
        : "=r"(r[0]), "=r"(r[1]) : "r"(addr));
}
__device__ __forceinline__ void mma_f16(float* c, const uint32_t* a, const uint32_t* b) {
    asm volatile("mma.sync.aligned.m16n8k16.row.col.f32.f16.f16.f32 "
        "{%0,%1,%2,%3}, {%4,%5,%6,%7}, {%8,%9}, {%0,%1,%2,%3};"
        : "+f"(c[0]), "+f"(c[1]), "+f"(c[2]), "+f"(c[3])
        : "r"(a[0]), "r"(a[1]), "r"(a[2]), "r"(a[3]), "r"(b[0]), "r"(b[1]));
}

__device__ __forceinline__ uint32_t pack_hi(float x, float y) {
    union { __half2 h2; uint32_t u; } H;
    H.h2 = __halves2half2(__float2half_rn(x), __float2half_rn(y));
    return H.u;
}

__device__ __forceinline__ float fexp2(float x) {
    x = fmaxf(x, -126.0f);
    int e = __float2int_rn(x);
    float f = x - (float)e;
    float p = 0.0018775767f;
    p = fmaf(p, f, 0.0089893397f);
    p = fmaf(p, f, 0.0558040221f);
    p = fmaf(p, f, 0.2402264923f);
    p = fmaf(p, f, 0.6931471825f);
    p = fmaf(p, f, 1.0f);
    return __int_as_float(__float_as_int(p) + (e << 23));
}

__device__ __forceinline__ void split_f16(float v, __half* hi, __half* lo) {
    __half h = __float2half_rn(v);
    *hi = h;
    *lo = __float2half_rn(v - __half2float(h));
}

__device__ __forceinline__ void rope_pair(float x1, float x2, int pos, int d,
                                          float& o1, float& o2)
{
    float inv = exp2f((float)d * (-13.287712379549449f / 64.0f));
    float ang = (float)pos * inv;
    float sn, cs;
    sincosf(ang, &sn, &cs);
    o1 = x1 * cs - x2 * sn;
    o2 = x1 * sn + x2 * cs;
}

// ---------------------------------------------------------------------------
__global__ void conv_split_kernel(const float* __restrict__ src,
                                  __half* __restrict__ hi,
                                  __half* __restrict__ lo)
{
    int i = blockIdx.x * 256 + threadIdx.x;
    float4 v = ((const float4*)src)[i];
    float f[4] = {v.x, v.y, v.z, v.w};
    union { uint2 u; __half b[4]; } H, L;
    #pragma unroll
    for (int j = 0; j < 4; ++j) split_f16(f[j], &H.b[j], &L.b[j]);
    ((uint2*)hi)[i] = H.u;
    ((uint2*)lo)[i] = L.u;
}

__global__ void transpose_half2_kernel(const float* __restrict__ W0,
                                       __half* __restrict__ O0,
                                       const float* __restrict__ W1,
                                       __half* __restrict__ O1,
                                       int Kd, int Nd)
{
    __shared__ float t[32][33];
    const float* W = blockIdx.z ? W1 : W0;
    __half* out    = blockIdx.z ? O1 : O0;
    int bn = blockIdx.x * 32;
    int bk = blockIdx.y * 32;
    int x = threadIdx.x, y = threadIdx.y;
    #pragma unroll
    for (int i = 0; i < 32; i += 8)
        t[y + i][x] = W[(size_t)(bk + y + i) * Nd + bn + x];
    __syncthreads();
    #pragma unroll
    for (int i = 0; i < 32; i += 8)
        out[(size_t)(bn + y + i) * Kd + bk + x] = __float2half_rn(t[x][y + i]);
}

// ---------------------------------------------------------------------------
// GEMM common
// ---------------------------------------------------------------------------
#define TILE_B   10240
#define BUF_B    (3*TILE_B)
#define GEMM_SMEM (3*BUF_B)

__device__ __forceinline__ void load_tile_async(uint32_t sdst,
                                                const __half* g,
                                                int ldk, int tid)
{
    int r   = tid >> 2;
    int seg = tid & 3;
    #pragma unroll
    for (int h = 0; h < 2; ++h) {
        int row = r + h * 64;
        cp16(sdst + row * 80 + seg * 16, g + (size_t)row * ldk + seg * 8);
    }
}

// ---------------------------------------------------------------------------
// QKV GEMM: (Ah+Al)@Bh^T, 2 products (unchanged from best)
// ---------------------------------------------------------------------------
__device__ __forceinline__ void load_stage(uint32_t buf,
                                           const __half* Ahi, const __half* Alo,
                                           const __half* Bh, int k0, int K, int tid)
{
    load_tile_async(buf,            Ahi + k0, K, tid);
    load_tile_async(buf +   TILE_B, Alo + k0, K, tid);
    load_tile_async(buf + 2*TILE_B, Bh  + k0, K, tid);
}

__device__ __forceinline__ void gemm_body(
    uint32_t sb,
    const __half* Ahi, const __half* Alo, const __half* Bh,
    float* C, int N, int K, int tid)
{
    const int lane = tid & 31, wid = tid >> 5;
    const int wm = wid & 1, wn = wid >> 1;

    float acc[4][4][4];
    #pragma unroll
    for (int mi = 0; mi < 4; ++mi)
        #pragma unroll
        for (int ni = 0; ni < 4; ++ni)
            #pragma unroll
            for (int q = 0; q < 4; ++q) acc[mi][ni][q] = 0.f;

    const int T = K / 32;
    load_stage(sb,         Ahi, Alo, Bh, 0,  K, tid);
    CP_COMMIT();
    load_stage(sb + BUF_B, Ahi, Alo, Bh, 32, K, tid);
    CP_COMMIT();

    const uint32_t a_lane_off = (uint32_t)((lane & 15) * 80 + (lane >> 4) * 16);
    const uint32_t b_lane_off = (uint32_t)((lane & 7) * 80 + ((lane >> 3) & 1) * 16);

    int bufidx = 0;
    for (int kt = 0; kt < T; ++kt) {
        if (kt < T - 1) { CP_WAIT(1); } else { CP_WAIT(0); }
        __syncthreads();

        if (kt + 2 < T) {
            int nbi = bufidx + 2; if (nbi >= 3) nbi -= 3;
            load_stage(sb + nbi * BUF_B, Ahi, Alo, Bh, (kt + 2) * 32, K, tid);
            CP_COMMIT();
        }

        uint32_t buf = sb + bufidx * BUF_B;
        #pragma unroll
        for (int ks = 0; ks < 2; ++ks) {
            uint32_t ah[4][4], al[4][4], bh[4][2];
            uint32_t abase = buf + wm * (64 * 80) + a_lane_off + ks * 32;
            #pragma unroll
            for (int mi = 0; mi < 4; ++mi) {
                ldm_x4(ah[mi], abase + mi * (16 * 80));
                ldm_x4(al[mi], abase + TILE_B + mi * (16 * 80));
            }
            uint32_t bbase = buf + 2*TILE_B + wn * (32 * 80) + b_lane_off + ks * 32;
            #pragma unroll
            for (int ni = 0; ni < 4; ++ni)
                ldm_x2(bh[ni], bbase + ni * (8 * 80));
            #pragma unroll
            for (int mi = 0; mi < 4; ++mi)
                #pragma unroll
                for (int ni = 0; ni < 4; ++ni)
                    mma_f16(acc[mi][ni], ah[mi], bh[ni]);
            #pragma unroll
            for (int mi = 0; mi < 4; ++mi)
                #pragma unroll
                for (int ni = 0; ni < 4; ++ni)
                    mma_f16(acc[mi][ni], al[mi], bh[ni]);
        }
        if (++bufidx == 3) bufidx = 0;
    }

    #pragma unroll
    for (int mi = 0; mi < 4; ++mi) {
        int row = wm * 64 + mi * 16 + (lane >> 2);
        #pragma unroll
        for (int ni = 0; ni < 4; ++ni) {
            int col = wn * 32 + ni * 8 + (lane & 3) * 2;
            *(float2*)&C[(size_t)row * N + col] =
                make_float2(acc[mi][ni][0], acc[mi][ni][1]);
            *(float2*)&C[(size_t)(row + 8) * N + col] =
                make_float2(acc[mi][ni][2], acc[mi][ni][3]);
        }
    }
}

__global__ __launch_bounds__(256, 2)
void qkv_gemm_kernel(const __half* __restrict__ Ahi,
                     const __half* __restrict__ Alo,
                     const __half* __restrict__ Wq,
                     const __half* __restrict__ Wk,
                     const __half* __restrict__ Wv,
                     float* __restrict__ Cq, float* __restrict__ Ck,
                     float* __restrict__ Cv)
{
    extern __shared__ char smp[];
    uint32_t sb = smem_to_u32(smp);
    const int nb = blockIdx.x;
    const int bm = blockIdx.y * 128;
    const __half* Bh;
    float* C;
    int N, bn;
    if (nb < 16)      { Bh = Wq; C = Cq; N = HID_; bn = nb * 128; }
    else if (nb < 20) { Bh = Wk; C = Ck; N = KVD_; bn = (nb - 16) * 128; }
    else              { Bh = Wv; C = Cv; N = KVD_; bn = (nb - 20) * 128; }
    gemm_body(sb,
              Ahi + (size_t)bm * HID_, Alo + (size_t)bm * HID_,
              Bh + (size_t)bn * HID_,
              C + (size_t)bm * N + bn, N, HID_, threadIdx.x);
}

// ---------------------------------------------------------------------------
// Wo GEMM: single product Ah@Bh^T (A = fp16 attention out)
// ---------------------------------------------------------------------------
#define BUF1_B (2*TILE_B)
#define GEMM1_SMEM (3*BUF1_B)   // 61440

__global__ __launch_bounds__(256, 2)
void gemm1_mma_kernel(const __half* __restrict__ A,
                      const __half* __restrict__ Bh,
                      float* __restrict__ C, int N, int K)
{
    extern __shared__ char smp[];
    uint32_t sb = smem_to_u32(smp);
    const int tid = threadIdx.x;
    const int lane = tid & 31, wid = tid >> 5;
    const int wm = wid & 1, wn = wid >> 1;
    const int bm = blockIdx.y * 128, bn = blockIdx.x * 128;
    const __half* Ab = A + (size_t)bm * K;
    const __half* Bb = Bh + (size_t)bn * K;

    float acc[4][4][4];
    #pragma unroll
    for (int mi = 0; mi < 4; ++mi)
        #pragma unroll
        for (int ni = 0; ni < 4; ++ni)
            #pragma unroll
            for (int q = 0; q < 4; ++q) acc[mi][ni][q] = 0.f;

    const int T = K / 32;
    load_tile_async(sb,                   Ab,      K, tid);
    load_tile_async(sb + TILE_B,          Bb,      K, tid);
    CP_COMMIT();
    load_tile_async(sb + BUF1_B,          Ab + 32, K, tid);
    load_tile_async(sb + BUF1_B + TILE_B, Bb + 32, K, tid);
    CP_COMMIT();

    const uint32_t a_lane_off = (uint32_t)((lane & 15) * 80 + (lane >> 4) * 16);
    const uint32_t b_lane_off = (uint32_t)((lane & 7) * 80 + ((lane >> 3) & 1) * 16);

    int bufidx = 0;
    for (int kt = 0; kt < T; ++kt) {
        if (kt < T - 1) { CP_WAIT(1); } else { CP_WAIT(0); }
        __syncthreads();

        if (kt + 2 < T) {
            int nbi = bufidx + 2; if (nbi >= 3) nbi -= 3;
            uint32_t nb_ = sb + nbi * BUF1_B;
            int k0 = (kt + 2) * 32;
            load_tile_async(nb_,          Ab + k0, K, tid);
            load_tile_async(nb_ + TILE_B, Bb + k0, K, tid);
            CP_COMMIT();
        }

        uint32_t buf = sb + bufidx * BUF1_B;
        #pragma unroll
        for (int ks = 0; ks < 2; ++ks) {
            uint32_t ah[4][4], bh[4][2];
            uint32_t abase = buf + wm * (64 * 80) + a_lane_off + ks * 32;
            #pragma unroll
            for (int mi = 0; mi < 4; ++mi)
                ldm_x4(ah[mi], abase + mi * (16 * 80));
            uint32_t bbase = buf + TILE_B + wn * (32 * 80) + b_lane_off + ks * 32;
            #pragma unroll
            for (int ni = 0; ni < 4; ++ni)
                ldm_x2(bh[ni], bbase + ni * (8 * 80));
            #pragma unroll
            for (int mi = 0; mi < 4; ++mi)
                #pragma unroll
                for (int ni = 0; ni < 4; ++ni)
                    mma_f16(acc[mi][ni], ah[mi], bh[ni]);
        }
        if (++bufidx == 3) bufidx = 0;
    }

    float* Cb = C + (size_t)bm * N + bn;
    #pragma unroll
    for (int mi = 0; mi < 4; ++mi) {
        int row = wm * 64 + mi * 16 + (lane >> 2);
        #pragma unroll
        for (int ni = 0; ni < 4; ++ni) {
            int col = wn * 32 + ni * 8 + (lane & 3) * 2;
            *(float2*)&Cb[(size_t)row * N + col] =
                make_float2(acc[mi][ni][0], acc[mi][ni][1]);
            *(float2*)&Cb[(size_t)(row + 8) * N + col] =
                make_float2(acc[mi][ni][2], acc[mi][ni][3]);
        }
    }
}

// ---------------------------------------------------------------------------
// RoPE / layout kernels
// ---------------------------------------------------------------------------
__global__ void rope_q_kernel(const int* __restrict__ positions,
                              __half* __restrict__ qh,
                              __half* __restrict__ ql)
{
    int idx = blockIdx.x * blockDim.x + threadIdx.x;
    int d = idx & 63;
    int s = (idx >> 6) & (S_ - 1);
    int h = idx >> 17;
    size_t base = (size_t)s * HID_ + h * HD_;
    float x1 = g_q[base + d], x2 = g_q[base + d + 64];
    float o1, o2;
    rope_pair(x1, x2, positions[s], d, o1, o2);
    o1 *= SCL_LOG2E; o2 *= SCL_LOG2E;
    split_f16(o1, &qh[base + d],      &ql[base + d]);
    split_f16(o2, &qh[base + d + 64], &ql[base + d + 64]);
}

__global__ void rope_k_kernel(const int* __restrict__ positions,
                              float* __restrict__ kout,
                              __half* __restrict__ kb)
{
    int idx = blockIdx.x * blockDim.x + threadIdx.x;
    int d  = idx & 63;
    int s  = (idx >> 6) & (S_ - 1);
    int kv = idx >> 17;
    size_t src = (size_t)s * KVD_ + kv * HD_;
    float x1 = g_k[src + d], x2 = g_k[src + d + 64];
    float o1, o2;
    rope_pair(x1, x2, positions[s], d, o1, o2);
    #pragma unroll
    for (int g = 0; g < GRP_; ++g) {
        size_t dst = ((size_t)(kv * GRP_ + g) * S_ + s) * HD_;
        kout[dst + d] = o1; kout[dst + d + 64] = o2;
    }
    size_t cb = ((size_t)kv * S_ + s) * HD_;
    kb[cb + d]      = __float2half_rn(o1);
    kb[cb + d + 64] = __float2half_rn(o2);
}

__global__ void copy_v_kernel(float* __restrict__ vout,
                              __half* __restrict__ vb)
{
    int idx = blockIdx.x * blockDim.x + threadIdx.x;
    int d4 = idx & 31;
    int s  = (idx >> 5) & (S_ - 1);
    int kv = idx >> 16;
    float4 v = *(const float4*)&g_v[(size_t)s * KVD_ + kv * HD_ + d4 * 4];
    #pragma unroll
    for (int g = 0; g < GRP_; ++g)
        *(float4*)&vout[((size_t)(kv * GRP_ + g) * S_ + s) * HD_ + d4 * 4] = v;
    size_t cb = ((size_t)kv * S_ + s) * HD_ + d4 * 4;
    float f[4] = {v.x, v.y, v.z, v.w};
    union { uint2 u; __half b[4]; } H;
    #pragma unroll
    for (int j = 0; j < 4; ++j) H.b[j] = __float2half_rn(f[j]);
    *(uint2*)&vb[cb] = H.u;
}

// ---------------------------------------------------------------------------
// Tensor-core flash attention: BQ=64, BK=64, HD=128, 4 warps, 2 CTAs/SM.
// QK 2-product; PV single product (Ph*Vh). Output: fp16 single.
// ---------------------------------------------------------------------------
#define FSTR  272
#define FQ_B  (64*FSTR)
#define FKV_B (64*FSTR)
#define FLASH_SMEM (2*FQ_B + 4*FKV_B)   // 104448

__global__ __launch_bounds__(128, 2)
void flash_tc_kernel(const __half* __restrict__ qhp,
                     const __half* __restrict__ qlp,
                     const __half* __restrict__ khp,
                     const __half* __restrict__ vhp,
                     __half* __restrict__ at)
{
    extern __shared__ char smp[];
    const uint32_t sb = smem_to_u32(smp);
    const int tid = threadIdx.x, lane = tid & 31, w = tid >> 5;
    const int qb = 31 - blockIdx.x, h = blockIdx.y, kv = h >> 2;
    const int q0 = qb * 64;

    const uint32_t sQh = sb, sQl = sb + FQ_B;
    const uint32_t sKV = sb + 2 * FQ_B;

    {
        const __half* srch = qhp + (size_t)q0 * HID_ + h * HD_;
        const __half* srcl = qlp + (size_t)q0 * HID_ + h * HD_;
        #pragma unroll
        for (int c = tid; c < 1024; c += 128) {
            int r = c >> 4, seg = c & 15;
            cp16(sQh + r * FSTR + seg * 16, srch + (size_t)r * HID_ + seg * 8);
            cp16(sQl + r * FSTR + seg * 16, srcl + (size_t)r * HID_ + seg * 8);
        }
    }
    const __half* kb = khp + (size_t)kv * S_ * HD_;
    const __half* vb = vhp + (size_t)kv * S_ * HD_;

    auto load_kv = [&](int kt, uint32_t buf) {
        #pragma unroll
        for (int c = tid; c < 1024; c += 128) {
            int r = c >> 4, seg = c & 15;
            size_t g = (size_t)(kt * 64 + r) * HD_ + seg * 8;
            uint32_t so = r * FSTR + seg * 16;
            cp16(buf + so,         kb + g);
            cp16(buf + FKV_B + so, vb + g);
        }
    };
    load_kv(0, sKV);
    CP_COMMIT();

    float o[16][4];
    #pragma unroll
    for (int j = 0; j < 16; ++j)
        #pragma unroll
        for (int q = 0; q < 4; ++q) o[j][q] = 0.f;
    float m0 = -1e30f, m1 = -1e30f, l0 = 0.f, l1 = 0.f;

    const int last = qb;
    const uint32_t a_off  = (lane & 15) * FSTR + (lane >> 4) * 16;
    const uint32_t bk_off = (lane & 7) * FSTR + ((lane >> 3) & 1) * 16;
    const uint32_t bv_off = (lane & 15) * FSTR;
    const int r0 = q0 + w * 16 + (lane >> 2);

    for (int kt = 0; kt <= last; ++kt) {
        if (kt < last) {
            load_kv(kt + 1, sKV + ((kt + 1) & 1) * 2 * FKV_B);
            CP_COMMIT();
            CP_WAIT(1);
        } else {
            CP_WAIT(0);
        }
        __syncthreads();

        const uint32_t bK = sKV + (kt & 1) * 2 * FKV_B;
        const uint32_t bV = bK + FKV_B;

        // ---- scores S = (Qh+Ql) Kh^T ----
        float s[8][4];
        #pragma unroll
        for (int j = 0; j < 8; ++j)
            #pragma unroll
            for (int q = 0; q < 4; ++q) s[j][q] = 0.f;

        #pragma unroll
        for (int ks = 0; ks < 8; ++ks) {
            uint32_t ah[4], al[4], bh2[8][2];
            ldm_x4(ah, sQh + w * (16 * FSTR) + a_off + ks * 32);
            ldm_x4(al, sQl + w * (16 * FSTR) + a_off + ks * 32);
            #pragma unroll
            for (int j = 0; j < 8; ++j)
                ldm_x2(bh2[j], bK + j * (8 * FSTR) + bk_off + ks * 32);
            #pragma unroll
            for (int j = 0; j < 8; ++j)
                mma_f16(s[j], ah, bh2[j]);
            #pragma unroll
            for (int j = 0; j < 8; ++j)
                mma_f16(s[j], al, bh2[j]);
        }

        // ---- causal mask (diagonal block only) ----
        if (kt == qb) {
            #pragma unroll
            for (int j = 0; j < 8; ++j) {
                int col = kt * 64 + j * 8 + (lane & 3) * 2;
                if (col     > r0)     s[j][0] = -3e4f;
                if (col + 1 > r0)     s[j][1] = -3e4f;
                if (col     > r0 + 8) s[j][2] = -3e4f;
                if (col + 1 > r0 + 8) s[j][3] = -3e4f;
            }
        }

        // ---- row max ----
        float mx0 = -3e4f, mx1 = -3e4f;
        #pragma unroll
        for (int j = 0; j < 8; ++j) {
            mx0 = fmaxf(mx0, fmaxf(s[j][0], s[j][1]));
            mx1 = fmaxf(mx1, fmaxf(s[j][2], s[j][3]));
        }
        mx0 = fmaxf(mx0, __shfl_xor_sync(0xffffffffu, mx0, 1));
        mx0 = fmaxf(mx0, __shfl_xor_sync(0xffffffffu, mx0, 2));
        mx1 = fmaxf(mx1, __shfl_xor_sync(0xffffffffu, mx1, 1));
        mx1 = fmaxf(mx1, __shfl_xor_sync(0xffffffffu, mx1, 2));

        const float mn0 = fmaxf(m0, mx0), mn1 = fmaxf(m1, mx1);
        const float al0 = fexp2(m0 - mn0), al1 = fexp2(m1 - mn1);
        m0 = mn0; m1 = mn1;

        // ---- exp + row sum ----
        float sum0 = 0.f, sum1 = 0.f;
        #pragma unroll
        for (int j = 0; j < 8; ++j) {
            s[j][0] = fexp2(s[j][0] - mn0);
            s[j][1] = fexp2(s[j][1] - mn0);
            s[j][2] = fexp2(s[j][2] - mn1);
            s[j][3] = fexp2(s[j][3] - mn1);
            sum0 += s[j][0] + s[j][1];
            sum1 += s[j][2] + s[j][3];
        }
        sum0 += __shfl_xor_sync(0xffffffffu, sum0, 1);
        sum0 += __shfl_xor_sync(0xffffffffu, sum0, 2);
        sum1 += __shfl_xor_sync(0xffffffffu, sum1, 1);
        sum1 += __shfl_xor_sync(0xffffffffu, sum1, 2);
        l0 = l0 * al0 + sum0;
        l1 = l1 * al1 + sum1;

        // ---- rescale O ----
        #pragma unroll
        for (int j = 0; j < 16; ++j) {
            o[j][0] *= al0; o[j][1] *= al0;
            o[j][2] *= al1; o[j][3] *= al1;
        }

        // ---- O += Ph Vh (single product) ----
        #pragma unroll
        for (int pk = 0; pk < 4; ++pk) {
            uint32_t phi[4], vv[16][2];
            phi[0] = pack_hi(s[2*pk][0],   s[2*pk][1]);
            phi[1] = pack_hi(s[2*pk][2],   s[2*pk][3]);
            phi[2] = pack_hi(s[2*pk+1][0], s[2*pk+1][1]);
            phi[3] = pack_hi(s[2*pk+1][2], s[2*pk+1][3]);
            #pragma unroll
            for (int j = 0; j < 16; ++j) {
                ldm_x2t(vv[j], bV + pk * (16 * FSTR) + bv_off + j * 16);
                mma_f16(o[j], phi, vv[j]);
            }
        }
        __syncthreads();
    }

    // ---- epilogue: normalize, write fp16 ----
    const float inv0 = 1.f / l0, inv1 = 1.f / l1;
    #pragma unroll
    for (int j = 0; j < 16; ++j) {
        int col = j * 8 + (lane & 3) * 2;
        size_t off0 = (size_t)r0 * HID_ + h * HD_ + col;
        *(uint32_t*)&at[off0] = pack_hi(o[j][0] * inv0, o[j][1] * inv0);
        size_t off1 = (size_t)(r0 + 8) * HID_ + h * HD_ + col;
        *(uint32_t*)&at[off1] = pack_hi(o[j][2] * inv1, o[j][3] * inv1);
    }
}

// ---------------------------------------------------------------------------
extern "C" void kernel_launch(void* const* d_in, const int* in_sizes, int n_in,
                              void* d_out, int out_size)
{
    const float* hs  = (const float*)d_in[0];
    const int*   pos = (const int*)  d_in[1];
    const float* Wq  = (const float*)d_in[3];
    const float* Wk  = (const float*)d_in[4];
    const float* Wv  = (const float*)d_in[5];
    const float* Wo  = (const float*)d_in[6];

    float* out  = (float*)d_out;
    float* kout = out  + (size_t)S_ * HID_;
    float* vout = kout + (size_t)NH_ * S_ * HD_;

    float *qp, *kp, *vp;
    cudaGetSymbolAddress((void**)&qp, g_q);
    cudaGetSymbolAddress((void**)&kp, g_k);
    cudaGetSymbolAddress((void**)&vp, g_v);
    __half *hsh, *hsl, *wq, *wk, *wv, *wo, *at;
    __half *qbh, *qbl, *kb, *vb;
    cudaGetSymbolAddress((void**)&hsh, g_hs_hi); cudaGetSymbolAddress((void**)&hsl, g_hs_lo);
    cudaGetSymbolAddress((void**)&wq, g_wq);
    cudaGetSymbolAddress((void**)&wk, g_wk);
    cudaGetSymbolAddress((void**)&wv, g_wv);
    cudaGetSymbolAddress((void**)&wo, g_wo);
    cudaGetSymbolAddress((void**)&at, g_at);
    cudaGetSymbolAddress((void**)&qbh, g_qb_hi); cudaGetSymbolAddress((void**)&qbl, g_qb_lo);
    cudaGetSymbolAddress((void**)&kb, g_kb);
    cudaGetSymbolAddress((void**)&vb, g_vb);

    cudaFuncSetAttribute(qkv_gemm_kernel,
                         cudaFuncAttributeMaxDynamicSharedMemorySize, GEMM_SMEM);
    cudaFuncSetAttribute(gemm1_mma_kernel,
                         cudaFuncAttributeMaxDynamicSharedMemorySize, GEMM1_SMEM);
    cudaFuncSetAttribute(flash_tc_kernel,
                         cudaFuncAttributeMaxDynamicSharedMemorySize, FLASH_SMEM);

    conv_split_kernel<<<(S_*HID_/4)/256, 256>>>(hs, hsh, hsl);
    transpose_half2_kernel<<<dim3(HID_/32, HID_/32, 2), dim3(32,8)>>>(
        Wq, wq, Wo, wo, HID_, HID_);
    transpose_half2_kernel<<<dim3(KVD_/32, HID_/32, 2), dim3(32,8)>>>(
        Wk, wk, Wv, wv, HID_, KVD_);

    qkv_gemm_kernel<<<dim3(24, S_/128), 256, GEMM_SMEM>>>(
        hsh, hsl, wq, wk, wv, qp, kp, vp);

    rope_q_kernel<<<(NH_*S_*64)/256, 256>>>(pos, qbh, qbl);
    rope_k_kernel<<<(NKV_*S_*64)/256, 256>>>(pos, kout, kb);
    copy_v_kernel<<<(NKV_*S_*32)/256, 256>>>(vout, vb);

    flash_tc_kernel<<<dim3(32, NH_), 128, FLASH_SMEM>>>(
        qbh, qbl, kb, vb, at);

    // Wo: single-product fp16 GEMM
    gemm1_mma_kernel<<<dim3(HID_/128, S_/128), 256, GEMM1_SMEM>>>(
        at, wo, out, HID_, HID_);
}

// round 14
// speedup vs baseline: 1.5865x; 1.1894x over previous
#include <cuda_runtime.h>
#include <cuda_fp16.h>
#include <math.h>
#include <stdint.h>

#define S_   2048
#define HID_ 2048
#define NH_  16
#define NKV_ 4
#define GRP_ (NH_/NKV_)   // 4
#define HD_  128
#define KVD_ (NKV_*HD_)   // 512

#define SCL_LOG2E 0.12751744f

// ---------------------------------------------------------------------------
// scratch (allocation-free: __device__ globals)
// ---------------------------------------------------------------------------
__device__ float g_q  [S_*HID_];
__device__ float g_k  [S_*KVD_];
__device__ float g_v  [S_*KVD_];

__device__ __half g_hs[S_*HID_];          // hidden, single fp16
__device__ __half g_wq[HID_*HID_];
__device__ __half g_wk[KVD_*HID_];
__device__ __half g_wv[KVD_*HID_];
__device__ __half g_wo[HID_*HID_];
__device__ __half g_at[S_*HID_];          // attn out, single fp16

__device__ __half g_qb_hi[S_*HID_],  g_qb_lo[S_*HID_];
__device__ __half g_kb[NKV_*S_*HD_];
__device__ __half g_vb[NKV_*S_*HD_];

// ---------------------------------------------------------------------------
// PTX helpers (plain sm_103-safe)
// ---------------------------------------------------------------------------
__device__ __forceinline__ uint32_t smem_to_u32(const void* p) {
    uint32_t a;
    asm("{ .reg .u64 t; cvta.to.shared.u64 t, %1; cvt.u32.u64 %0, t; }"
        : "=r"(a) : "l"(p));
    return a;
}
__device__ __forceinline__ void cp16(uint32_t dst, const void* src) {
    asm volatile("cp.async.cg.shared.global [%0], [%1], 16;" :: "r"(dst), "l"(src));
}
#define CP_COMMIT() asm volatile("cp.async.commit_group;" ::: "memory")
#define CP_WAIT(n)  asm volatile("cp.async.wait_group %0;" :: "n"(n) : "memory")

__device__ __forceinline__ void ldm_x4(uint32_t* r, uint32_t addr) {
    asm volatile("ldmatrix.sync.aligned.m8n8.x4.shared.b16 {%0,%1,%2,%3}, [%4];"
        : "=r"(r[0]), "=r"(r[1]), "=r"(r[2]), "=r"(r[3]) : "r"(addr));
}
__device__ __forceinline__ void ldm_x2(uint32_t* r, uint32_t addr) {
    asm volatile("ldmatrix.sync.aligned.m8n8.x2.shared.b16 {%0,%1}, [%2];"
        : "=r"(r[0]), "=r"(r[1]) : "r"(addr));
}
__device__ __forceinline__ void ldm_x2t(uint32_t* r, uint32_t addr) {
    asm volatile("ldmatrix.sync.aligned.m8n8.x2.trans.shared.b16 {%0,%1}, [%2];"
        : "=r"(r[0]), "=r"(r[1]) : "r"(addr));
}
__device__ __forceinline__ void mma_f16(float* c, const uint32_t* a, const uint32_t* b) {
    asm volatile("mma.sync.aligned.m16n8k16.row.col.f32.f16.f16.f32 "
        "{%0,%1,%2,%3}, {%4,%5,%6,%7}, {%8,%9}, {%0,%1,%2,%3};"
        : "+f"(c[0]), "+f"(c[1]), "+f"(c[2]), "+f"(c[3])
        : "r"(a[0]), "r"(a[1]), "r"(a[2]), "r"(a[3]), "r"(b[0]), "r"(b[1]));
}

__device__ __forceinline__ uint32_t pack_hi(float x, float y) {
    union { __half2 h2; uint32_t u; } H;
    H.h2 = __halves2half2(__float2half_rn(x), __float2half_rn(y));
    return H.u;
}

__device__ __forceinline__ float fexp2(float x) {
    x = fmaxf(x, -126.0f);
    int e = __float2int_rn(x);
    float f = x - (float)e;
    float p = 0.0018775767f;
    p = fmaf(p, f, 0.0089893397f);
    p = fmaf(p, f, 0.0558040221f);
    p = fmaf(p, f, 0.2402264923f);
    p = fmaf(p, f, 0.6931471825f);
    p = fmaf(p, f, 1.0f);
    return __int_as_float(__float_as_int(p) + (e << 23));
}

__device__ __forceinline__ void split_f16(float v, __half* hi, __half* lo) {
    __half h = __float2half_rn(v);
    *hi = h;
    *lo = __float2half_rn(v - __half2float(h));
}

__device__ __forceinline__ void rope_pair(float x1, float x2, int pos, int d,
                                          float& o1, float& o2)
{
    float inv = exp2f((float)d * (-13.287712379549449f / 64.0f));
    float ang = (float)pos * inv;
    float sn, cs;
    sincosf(ang, &sn, &cs);
    o1 = x1 * cs - x2 * sn;
    o2 = x1 * sn + x2 * cs;
}

// ---------------------------------------------------------------------------
__global__ void conv_half_kernel(const float* __restrict__ src,
                                 __half* __restrict__ dst)
{
    int i = blockIdx.x * 256 + threadIdx.x;
    float4 v = ((const float4*)src)[i];
    union { uint2 u; __half b[4]; } H;
    H.b[0] = __float2half_rn(v.x); H.b[1] = __float2half_rn(v.y);
    H.b[2] = __float2half_rn(v.z); H.b[3] = __float2half_rn(v.w);
    ((uint2*)dst)[i] = H.u;
}

__global__ void transpose_half2_kernel(const float* __restrict__ W0,
                                       __half* __restrict__ O0,
                                       const float* __restrict__ W1,
                                       __half* __restrict__ O1,
                                       int Kd, int Nd)
{
    __shared__ float t[32][33];
    const float* W = blockIdx.z ? W1 : W0;
    __half* out    = blockIdx.z ? O1 : O0;
    int bn = blockIdx.x * 32;
    int bk = blockIdx.y * 32;
    int x = threadIdx.x, y = threadIdx.y;
    #pragma unroll
    for (int i = 0; i < 32; i += 8)
        t[y + i][x] = W[(size_t)(bk + y + i) * Nd + bn + x];
    __syncthreads();
    #pragma unroll
    for (int i = 0; i < 32; i += 8)
        out[(size_t)(bn + y + i) * Kd + bk + x] = __float2half_rn(t[x][y + i]);
}

// ---------------------------------------------------------------------------
// 1-product fp16 GEMM body: C = A @ Bh^T.  128x128 tile, K-chunks of 32,
// 3-stage cp.async, 2 CTAs/SM.
// ---------------------------------------------------------------------------
#define TILE_B   10240
#define BUF1_B   (2*TILE_B)
#define GEMM1_SMEM (3*BUF1_B)   // 61440

__device__ __forceinline__ void load_tile_async(uint32_t sdst,
                                                const __half* g,
                                                int ldk, int tid)
{
    int r   = tid >> 2;
    int seg = tid & 3;
    #pragma unroll
    for (int h = 0; h < 2; ++h) {
        int row = r + h * 64;
        cp16(sdst + row * 80 + seg * 16, g + (size_t)row * ldk + seg * 8);
    }
}

__device__ __forceinline__ void gemm1_body(
    uint32_t sb,
    const __half* A, const __half* Bh,
    float* C, int N, int K, int tid)
{
    const int lane = tid & 31, wid = tid >> 5;
    const int wm = wid & 1, wn = wid >> 1;

    float acc[4][4][4];
    #pragma unroll
    for (int mi = 0; mi < 4; ++mi)
        #pragma unroll
        for (int ni = 0; ni < 4; ++ni)
            #pragma unroll
            for (int q = 0; q < 4; ++q) acc[mi][ni][q] = 0.f;

    const int T = K / 32;
    load_tile_async(sb,                   A,      K, tid);
    load_tile_async(sb + TILE_B,          Bh,     K, tid);
    CP_COMMIT();
    load_tile_async(sb + BUF1_B,          A + 32, K, tid);
    load_tile_async(sb + BUF1_B + TILE_B, Bh + 32, K, tid);
    CP_COMMIT();

    const uint32_t a_lane_off = (uint32_t)((lane & 15) * 80 + (lane >> 4) * 16);
    const uint32_t b_lane_off = (uint32_t)((lane & 7) * 80 + ((lane >> 3) & 1) * 16);

    int bufidx = 0;
    for (int kt = 0; kt < T; ++kt) {
        if (kt < T - 1) { CP_WAIT(1); } else { CP_WAIT(0); }
        __syncthreads();

        if (kt + 2 < T) {
            int nbi = bufidx + 2; if (nbi >= 3) nbi -= 3;
            uint32_t nb_ = sb + nbi * BUF1_B;
            int k0 = (kt + 2) * 32;
            load_tile_async(nb_,          A + k0,  K, tid);
            load_tile_async(nb_ + TILE_B, Bh + k0, K, tid);
            CP_COMMIT();
        }

        uint32_t buf = sb + bufidx * BUF1_B;
        #pragma unroll
        for (int ks = 0; ks < 2; ++ks) {
            uint32_t ah[4][4], bh[4][2];
            uint32_t abase = buf + wm * (64 * 80) + a_lane_off + ks * 32;
            #pragma unroll
            for (int mi = 0; mi < 4; ++mi)
                ldm_x4(ah[mi], abase + mi * (16 * 80));
            uint32_t bbase = buf + TILE_B + wn * (32 * 80) + b_lane_off + ks * 32;
            #pragma unroll
            for (int ni = 0; ni < 4; ++ni)
                ldm_x2(bh[ni], bbase + ni * (8 * 80));
            #pragma unroll
            for (int mi = 0; mi < 4; ++mi)
                #pragma unroll
                for (int ni = 0; ni < 4; ++ni)
                    mma_f16(acc[mi][ni], ah[mi], bh[ni]);
        }
        if (++bufidx == 3) bufidx = 0;
    }

    #pragma unroll
    for (int mi = 0; mi < 4; ++mi) {
        int row = wm * 64 + mi * 16 + (lane >> 2);
        #pragma unroll
        for (int ni = 0; ni < 4; ++ni) {
            int col = wn * 32 + ni * 8 + (lane & 3) * 2;
            *(float2*)&C[(size_t)row * N + col] =
                make_float2(acc[mi][ni][0], acc[mi][ni][1]);
            *(float2*)&C[(size_t)(row + 8) * N + col] =
                make_float2(acc[mi][ni][2], acc[mi][ni][3]);
        }
    }
}

// fused QKV projection (1-product fp16)
__global__ __launch_bounds__(256, 2)
void qkv_gemm_kernel(const __half* __restrict__ A,
                     const __half* __restrict__ Wq,
                     const __half* __restrict__ Wk,
                     const __half* __restrict__ Wv,
                     float* __restrict__ Cq, float* __restrict__ Ck,
                     float* __restrict__ Cv)
{
    extern __shared__ char smp[];
    uint32_t sb = smem_to_u32(smp);
    const int nb = blockIdx.x;
    const int bm = blockIdx.y * 128;
    const __half* Bh;
    float* C;
    int N, bn;
    if (nb < 16)      { Bh = Wq; C = Cq; N = HID_; bn = nb * 128; }
    else if (nb < 20) { Bh = Wk; C = Ck; N = KVD_; bn = (nb - 16) * 128; }
    else              { Bh = Wv; C = Cv; N = KVD_; bn = (nb - 20) * 128; }
    gemm1_body(sb,
               A + (size_t)bm * HID_, Bh + (size_t)bn * HID_,
               C + (size_t)bm * N + bn, N, HID_, threadIdx.x);
}

// Wo projection (1-product fp16)
__global__ __launch_bounds__(256, 2)
void gemm1_mma_kernel(const __half* __restrict__ A,
                      const __half* __restrict__ Bh,
                      float* __restrict__ C, int N, int K)
{
    extern __shared__ char smp[];
    uint32_t sb = smem_to_u32(smp);
    const int bm = blockIdx.y * 128, bn = blockIdx.x * 128;
    gemm1_body(sb,
               A + (size_t)bm * K, Bh + (size_t)bn * K,
               C + (size_t)bm * N + bn, N, K, threadIdx.x);
}

// ---------------------------------------------------------------------------
// RoPE / layout kernels
// ---------------------------------------------------------------------------
__global__ void rope_q_kernel(const int* __restrict__ positions,
                              __half* __restrict__ qh,
                              __half* __restrict__ ql)
{
    int idx = blockIdx.x * blockDim.x + threadIdx.x;
    int d = idx & 63;
    int s = (idx >> 6) & (S_ - 1);
    int h = idx >> 17;
    size_t base = (size_t)s * HID_ + h * HD_;
    float x1 = g_q[base + d], x2 = g_q[base + d + 64];
    float o1, o2;
    rope_pair(x1, x2, positions[s], d, o1, o2);
    o1 *= SCL_LOG2E; o2 *= SCL_LOG2E;
    split_f16(o1, &qh[base + d],      &ql[base + d]);
    split_f16(o2, &qh[base + d + 64], &ql[base + d + 64]);
}

__global__ void rope_k_kernel(const int* __restrict__ positions,
                              float* __restrict__ kout,
                              __half* __restrict__ kb)
{
    int idx = blockIdx.x * blockDim.x + threadIdx.x;
    int d  = idx & 63;
    int s  = (idx >> 6) & (S_ - 1);
    int kv = idx >> 17;
    size_t src = (size_t)s * KVD_ + kv * HD_;
    float x1 = g_k[src + d], x2 = g_k[src + d + 64];
    float o1, o2;
    rope_pair(x1, x2, positions[s], d, o1, o2);
    #pragma unroll
    for (int g = 0; g < GRP_; ++g) {
        size_t dst = ((size_t)(kv * GRP_ + g) * S_ + s) * HD_;
        kout[dst + d] = o1; kout[dst + d + 64] = o2;
    }
    size_t cb = ((size_t)kv * S_ + s) * HD_;
    kb[cb + d]      = __float2half_rn(o1);
    kb[cb + d + 64] = __float2half_rn(o2);
}

__global__ void copy_v_kernel(float* __restrict__ vout,
                              __half* __restrict__ vb)
{
    int idx = blockIdx.x * blockDim.x + threadIdx.x;
    int d4 = idx & 31;
    int s  = (idx >> 5) & (S_ - 1);
    int kv = idx >> 16;
    float4 v = *(const float4*)&g_v[(size_t)s * KVD_ + kv * HD_ + d4 * 4];
    #pragma unroll
    for (int g = 0; g < GRP_; ++g)
        *(float4*)&vout[((size_t)(kv * GRP_ + g) * S_ + s) * HD_ + d4 * 4] = v;
    size_t cb = ((size_t)kv * S_ + s) * HD_ + d4 * 4;
    float f[4] = {v.x, v.y, v.z, v.w};
    union { uint2 u; __half b[4]; } H;
    #pragma unroll
    for (int j = 0; j < 4; ++j) H.b[j] = __float2half_rn(f[j]);
    *(uint2*)&vb[cb] = H.u;
}

// ---------------------------------------------------------------------------
// Tensor-core flash attention: BQ=64, BK=64, HD=128, 4 warps, 2 CTAs/SM.
// QK 2-product (Q hi/lo); PV single product. Output fp16.
// ---------------------------------------------------------------------------
#define FSTR  272
#define FQ_B  (64*FSTR)
#define FKV_B (64*FSTR)
#define FLASH_SMEM (2*FQ_B + 4*FKV_B)   // 104448

__global__ __launch_bounds__(128, 2)
void flash_tc_kernel(const __half* __restrict__ qhp,
                     const __half* __restrict__ qlp,
                     const __half* __restrict__ khp,
                     const __half* __restrict__ vhp,
                     __half* __restrict__ at)
{
    extern __shared__ char smp[];
    const uint32_t sb = smem_to_u32(smp);
    const int tid = threadIdx.x, lane = tid & 31, w = tid >> 5;
    const int qb = 31 - blockIdx.x, h = blockIdx.y, kv = h >> 2;
    const int q0 = qb * 64;

    const uint32_t sQh = sb, sQl = sb + FQ_B;
    const uint32_t sKV = sb + 2 * FQ_B;

    {
        const __half* srch = qhp + (size_t)q0 * HID_ + h * HD_;
        const __half* srcl = qlp + (size_t)q0 * HID_ + h * HD_;
        #pragma unroll
        for (int c = tid; c < 1024; c += 128) {
            int r = c >> 4, seg = c & 15;
            cp16(sQh + r * FSTR + seg * 16, srch + (size_t)r * HID_ + seg * 8);
            cp16(sQl + r * FSTR + seg * 16, srcl + (size_t)r * HID_ + seg * 8);
        }
    }
    const __half* kb = khp + (size_t)kv * S_ * HD_;
    const __half* vb = vhp + (size_t)kv * S_ * HD_;

    auto load_kv = [&](int kt, uint32_t buf) {
        #pragma unroll
        for (int c = tid; c < 1024; c += 128) {
            int r = c >> 4, seg = c & 15;
            size_t g = (size_t)(kt * 64 + r) * HD_ + seg * 8;
            uint32_t so = r * FSTR + seg * 16;
            cp16(buf + so,         kb + g);
            cp16(buf + FKV_B + so, vb + g);
        }
    };
    load_kv(0, sKV);
    CP_COMMIT();

    float o[16][4];
    #pragma unroll
    for (int j = 0; j < 16; ++j)
        #pragma unroll
        for (int q = 0; q < 4; ++q) o[j][q] = 0.f;
    float m0 = -1e30f, m1 = -1e30f, l0 = 0.f, l1 = 0.f;

    const int last = qb;
    const uint32_t a_off  = (lane & 15) * FSTR + (lane >> 4) * 16;
    const uint32_t bk_off = (lane & 7) * FSTR + ((lane >> 3) & 1) * 16;
    const uint32_t bv_off = (lane & 15) * FSTR;
    const int r0 = q0 + w * 16 + (lane >> 2);

    for (int kt = 0; kt <= last; ++kt) {
        if (kt < last) {
            load_kv(kt + 1, sKV + ((kt + 1) & 1) * 2 * FKV_B);
            CP_COMMIT();
            CP_WAIT(1);
        } else {
            CP_WAIT(0);
        }
        __syncthreads();

        const uint32_t bK = sKV + (kt & 1) * 2 * FKV_B;
        const uint32_t bV = bK + FKV_B;

        float s[8][4];
        #pragma unroll
        for (int j = 0; j < 8; ++j)
            #pragma unroll
            for (int q = 0; q < 4; ++q) s[j][q] = 0.f;

        #pragma unroll
        for (int ks = 0; ks < 8; ++ks) {
            uint32_t ah[4], al[4], bh2[8][2];
            ldm_x4(ah, sQh + w * (16 * FSTR) + a_off + ks * 32);
            ldm_x4(al, sQl + w * (16 * FSTR) + a_off + ks * 32);
            #pragma unroll
            for (int j = 0; j < 8; ++j)
                ldm_x2(bh2[j], bK + j * (8 * FSTR) + bk_off + ks * 32);
            #pragma unroll
            for (int j = 0; j < 8; ++j)
                mma_f16(s[j], ah, bh2[j]);
            #pragma unroll
            for (int j = 0; j < 8; ++j)
                mma_f16(s[j], al, bh2[j]);
        }

        if (kt == qb) {
            #pragma unroll
            for (int j = 0; j < 8; ++j) {
                int col = kt * 64 + j * 8 + (lane & 3) * 2;
                if (col     > r0)     s[j][0] = -3e4f;
                if (col + 1 > r0)     s[j][1] = -3e4f;
                if (col     > r0 + 8) s[j][2] = -3e4f;
                if (col + 1 > r0 + 8) s[j][3] = -3e4f;
            }
        }

        float mx0 = -3e4f, mx1 = -3e4f;
        #pragma unroll
        for (int j = 0; j < 8; ++j) {
            mx0 = fmaxf(mx0, fmaxf(s[j][0], s[j][1]));
            mx1 = fmaxf(mx1, fmaxf(s[j][2], s[j][3]));
        }
        mx0 = fmaxf(mx0, __shfl_xor_sync(0xffffffffu, mx0, 1));
        mx0 = fmaxf(mx0, __shfl_xor_sync(0xffffffffu, mx0, 2));
        mx1 = fmaxf(mx1, __shfl_xor_sync(0xffffffffu, mx1, 1));
        mx1 = fmaxf(mx1, __shfl_xor_sync(0xffffffffu, mx1, 2));

        const float mn0 = fmaxf(m0, mx0), mn1 = fmaxf(m1, mx1);
        const float al0 = fexp2(m0 - mn0), al1 = fexp2(m1 - mn1);
        m0 = mn0; m1 = mn1;

        float sum0 = 0.f, sum1 = 0.f;
        #pragma unroll
        for (int j = 0; j < 8; ++j) {
            s[j][0] = fexp2(s[j][0] - mn0);
            s[j][1] = fexp2(s[j][1] - mn0);
            s[j][2] = fexp2(s[j][2] - mn1);
            s[j][3] = fexp2(s[j][3] - mn1);
            sum0 += s[j][0] + s[j][1];
            sum1 += s[j][2] + s[j][3];
        }
        sum0 += __shfl_xor_sync(0xffffffffu, sum0, 1);
        sum0 += __shfl_xor_sync(0xffffffffu, sum0, 2);
        sum1 += __shfl_xor_sync(0xffffffffu, sum1, 1);
        sum1 += __shfl_xor_sync(0xffffffffu, sum1, 2);
        l0 = l0 * al0 + sum0;
        l1 = l1 * al1 + sum1;

        #pragma unroll
        for (int j = 0; j < 16; ++j) {
            o[j][0] *= al0; o[j][1] *= al0;
            o[j][2] *= al1; o[j][3] *= al1;
        }

        #pragma unroll
        for (int pk = 0; pk < 4; ++pk) {
            uint32_t phi[4], vv[16][2];
            phi[0] = pack_hi(s[2*pk][0],   s[2*pk][1]);
            phi[1] = pack_hi(s[2*pk][2],   s[2*pk][3]);
            phi[2] = pack_hi(s[2*pk+1][0], s[2*pk+1][1]);
            phi[3] = pack_hi(s[2*pk+1][2], s[2*pk+1][3]);
            #pragma unroll
            for (int j = 0; j < 16; ++j) {
                ldm_x2t(vv[j], bV + pk * (16 * FSTR) + bv_off + j * 16);
                mma_f16(o[j], phi, vv[j]);
            }
        }
        __syncthreads();
    }

    const float inv0 = 1.f / l0, inv1 = 1.f / l1;
    #pragma unroll
    for (int j = 0; j < 16; ++j) {
        int col = j * 8 + (lane & 3) * 2;
        size_t off0 = (size_t)r0 * HID_ + h * HD_ + col;
        *(uint32_t*)&at[off0] = pack_hi(o[j][0] * inv0, o[j][1] * inv0);
        size_t off1 = (size_t)(r0 + 8) * HID_ + h * HD_ + col;
        *(uint32_t*)&at[off1] = pack_hi(o[j][2] * inv1, o[j][3] * inv1);
    }
}

// ---------------------------------------------------------------------------
extern "C" void kernel_launch(void* const* d_in, const int* in_sizes, int n_in,
                              void* d_out, int out_size)
{
    const float* hs  = (const float*)d_in[0];
    const int*   pos = (const int*)  d_in[1];
    const float* Wq  = (const float*)d_in[3];
    const float* Wk  = (const float*)d_in[4];
    const float* Wv  = (const float*)d_in[5];
    const float* Wo  = (const float*)d_in[6];

    float* out  = (float*)d_out;
    float* kout = out  + (size_t)S_ * HID_;
    float* vout = kout + (size_t)NH_ * S_ * HD_;

    float *qp, *kp, *vp;
    cudaGetSymbolAddress((void**)&qp, g_q);
    cudaGetSymbolAddress((void**)&kp, g_k);
    cudaGetSymbolAddress((void**)&vp, g_v);
    __half *hsp, *wq, *wk, *wv, *wo, *at;
    __half *qbh, *qbl, *kb, *vb;
    cudaGetSymbolAddress((void**)&hsp, g_hs);
    cudaGetSymbolAddress((void**)&wq, g_wq);
    cudaGetSymbolAddress((void**)&wk, g_wk);
    cudaGetSymbolAddress((void**)&wv, g_wv);
    cudaGetSymbolAddress((void**)&wo, g_wo);
    cudaGetSymbolAddress((void**)&at, g_at);
    cudaGetSymbolAddress((void**)&qbh, g_qb_hi); cudaGetSymbolAddress((void**)&qbl, g_qb_lo);
    cudaGetSymbolAddress((void**)&kb, g_kb);
    cudaGetSymbolAddress((void**)&vb, g_vb);

    cudaFuncSetAttribute(qkv_gemm_kernel,
                         cudaFuncAttributeMaxDynamicSharedMemorySize, GEMM1_SMEM);
    cudaFuncSetAttribute(gemm1_mma_kernel,
                         cudaFuncAttributeMaxDynamicSharedMemorySize, GEMM1_SMEM);
    cudaFuncSetAttribute(flash_tc_kernel,
                         cudaFuncAttributeMaxDynamicSharedMemorySize, FLASH_SMEM);

    conv_half_kernel<<<(S_*HID_/4)/256, 256>>>(hs, hsp);
    transpose_half2_kernel<<<dim3(HID_/32, HID_/32, 2), dim3(32,8)>>>(
        Wq, wq, Wo, wo, HID_, HID_);
    transpose_half2_kernel<<<dim3(KVD_/32, HID_/32, 2), dim3(32,8)>>>(
        Wk, wk, Wv, wv, HID_, KVD_);

    // fused QKV projection (1-product fp16)
    qkv_gemm_kernel<<<dim3(24, S_/128), 256, GEMM1_SMEM>>>(
        hsp, wq, wk, wv, qp, kp, vp);

    rope_q_kernel<<<(NH_*S_*64)/256, 256>>>(pos, qbh, qbl);
    rope_k_kernel<<<(NKV_*S_*64)/256, 256>>>(pos, kout, kb);
    copy_v_kernel<<<(NKV_*S_*32)/256, 256>>>(vout, vb);

    flash_tc_kernel<<<dim3(32, NH_), 128, FLASH_SMEM>>>(
        qbh, qbl, kb, vb, at);

    gemm1_mma_kernel<<<dim3(HID_/128, S_/128), 256, GEMM1_SMEM>>>(
        at, wo, out, HID_, HID_);
}